// round 8
// baseline (speedup 1.0000x reference)
#include <cuda_runtime.h>
#include <cstdint>

#define TDIM   1024
#define NSTEP  1023
#define IN_DIM 35

// output layout: coeff [256][1023][5] | mean [256][1023][5][32] | var [256][1023][5]
#define MEANBASE 1309440
#define VARBASE  43211520

// ---------------- device scratch (allocation-free) ----------------
// h history, k-pair interleaved: g_Hp[t][kp=128][b=256][2] ; elem (h[2kp][b], h[2kp+1][b])
__device__ float g_Hp[(size_t)NSTEP * 256 * 256];
__device__ float g_GX[(size_t)NSTEP * 1024 * 256];  // x-projection, [t][j=1024][b=256]
__device__ float g_W1t[256 * 112];                  // k-major, M padded 100->112
__device__ float g_W2t[112 * 112];
__device__ float g_W3t[112 * 176];                  // M padded 170->176
__device__ float g_b1p[112];
__device__ float g_b2p[112];
__device__ float g_b3p[176];
__device__ unsigned g_bar[8];

// ---------------- prep: barriers + MDN weight transposes ----------------
__global__ void prep_w(const float* __restrict__ W1, const float* __restrict__ b1,
                       const float* __restrict__ W2, const float* __restrict__ b2,
                       const float* __restrict__ W3, const float* __restrict__ b3)
{
    int id = blockIdx.x * blockDim.x + threadIdx.x;
    int stride = gridDim.x * blockDim.x;
    if (id < 8) g_bar[id] = 0u;
    for (int i = id; i < 256 * 112; i += stride) {
        int k = i / 112, m = i - k * 112;
        g_W1t[i] = (m < 100) ? W1[m * 256 + k] : 0.f;
    }
    for (int i = id; i < 112 * 112; i += stride) {
        int k = i / 112, m = i - k * 112;
        g_W2t[i] = (k < 100 && m < 100) ? W2[m * 100 + k] : 0.f;
    }
    for (int i = id; i < 112 * 176; i += stride) {
        int k = i / 176, m = i - k * 176;
        g_W3t[i] = (k < 100 && m < 170) ? W3[m * 100 + k] : 0.f;
    }
    for (int i = id; i < 112; i += stride) {
        g_b1p[i] = (i < 100) ? b1[i] : 0.f;
        g_b2p[i] = (i < 100) ? b2[i] : 0.f;
    }
    for (int i = id; i < 176; i += stride) g_b3p[i] = (i < 170) ? b3[i] : 0.f;
}

// ---------------- x-projection: GX[t][j][b] = sum_c W_ih[j][c] * x[b][t][c] ----------------
__global__ void __launch_bounds__(256)
xproj_kernel(const float* __restrict__ x, const float* __restrict__ W_ih)
{
    __shared__ float Ws[IN_DIM][64];
    __shared__ float xs[IN_DIM][64];
    const int tid = threadIdx.x;
    const int t  = blockIdx.x;
    const int jt = blockIdx.y;
    const int bt = blockIdx.z;

    for (int i = tid; i < 64 * IN_DIM; i += 256) {
        int m = i / IN_DIM, c = i - m * IN_DIM;
        Ws[c][m] = W_ih[(jt * 64 + m) * IN_DIM + c];
    }
    for (int i = tid; i < 64 * IN_DIM; i += 256) {
        int n = i / IN_DIM, c = i - n * IN_DIM;
        xs[c][n] = x[((size_t)(bt * 64 + n) * TDIM + t) * IN_DIM + c];
    }
    __syncthreads();

    const int tm = tid >> 4;
    const int tb = tid & 15;
    float acc[4][4];
#pragma unroll
    for (int i = 0; i < 4; ++i)
#pragma unroll
        for (int j = 0; j < 4; ++j) acc[i][j] = 0.f;
#pragma unroll 5
    for (int c = 0; c < IN_DIM; ++c) {
        float4 a  = *reinterpret_cast<const float4*>(&Ws[c][tm << 2]);
        float4 b4 = *reinterpret_cast<const float4*>(&xs[c][tb << 2]);
        float av[4] = {a.x, a.y, a.z, a.w};
        float bv[4] = {b4.x, b4.y, b4.z, b4.w};
#pragma unroll
        for (int i = 0; i < 4; ++i)
#pragma unroll
            for (int j = 0; j < 4; ++j) acc[i][j] = fmaf(av[i], bv[j], acc[i][j]);
    }
    float* dst = g_GX + (size_t)t * 262144 + (size_t)(jt * 64 + (tm << 2)) * 256
                 + bt * 64 + (tb << 2);
#pragma unroll
    for (int i = 0; i < 4; ++i)
        *reinterpret_cast<float4*>(dst + (size_t)i * 256) =
            make_float4(acc[i][0], acc[i][1], acc[i][2], acc[i][3]);
}

__device__ __forceinline__ float sigf(float v)     { return 1.f / (1.f + __expf(-v)); }
__device__ __forceinline__ float tanhfast(float v) { return 1.f - 2.f / (__expf(2.f * v) + 1.f); }

__device__ __forceinline__ float4 ldcg4(const float* p) {
    float4 v;
    asm volatile("ld.global.cg.v4.f32 {%0,%1,%2,%3},[%4];"
                 : "=f"(v.x), "=f"(v.y), "=f"(v.z), "=f"(v.w) : "l"(p));
    return v;
}
__device__ __forceinline__ void fma2(unsigned long long& d,
                                     unsigned long long a, unsigned long long b) {
    asm("fma.rn.f32x2 %0, %1, %2, %0;" : "+l"(d) : "l"(a), "l"(b));
}
__device__ __forceinline__ float lohi(unsigned long long v) {
    return __uint_as_float((unsigned)v) + __uint_as_float((unsigned)(v >> 32));
}

// ---------------- persistent LSTM ----------------
// grid 128: jg = blockIdx>>3 (16 hid-tiles of 16), bg = blockIdx&7 (8 batch-tiles of 32)
// 512 threads = 8 K-splits x 64; thread tile = 8 rows x 4 cols, k-pair FFMA2.
#define WKP_F  16384      // [kp=128][m=64] u64 pairs (floats x2)
#define HKP_F  8192       // [kp=128][n=32] u64 pairs
#define GST_LD 34
#define GST_F  (64 * GST_LD)
#define NSPLIT 8
#define LSTM_SMEM_BYTES ((WKP_F + HKP_F + NSPLIT*GST_F + 64 + 512 + 32) * 4)

__global__ void __launch_bounds__(512, 1)
lstm_kernel(const float* __restrict__ W_hh,
            const float* __restrict__ b_ih, const float* __restrict__ b_hh)
{
    extern __shared__ float sm[];
    float* Wkp  = sm;                  // k-pair interleaved weights
    float* hkp  = Wkp + WKP_F;         // k-pair interleaved h
    float* Gst  = hkp + HKP_F;         // 8 x [m=64][ld=34]
    float* bias = Gst + NSPLIT * GST_F;
    float* cS   = bias + 64;           // [16][32]

    const int tid = threadIdx.x;
    const int bg  = blockIdx.x & 7;
    const int jg  = blockIdx.x >> 3;

    // one-time weight staging: Wkp[kp][m] = (W[j][2kp], W[j][2kp+1])
    for (int i = tid; i < 128 * 64; i += 512) {
        int kp = i >> 6, m = i & 63;
        int j  = ((m >> 4) << 8) + (jg << 4) + (m & 15);   // gate*256 + jg*16 + jh
        float2 w = *reinterpret_cast<const float2*>(&W_hh[j * 256 + (kp << 1)]);
        *reinterpret_cast<float2*>(&Wkp[i << 1]) = w;
    }
    if (tid < 64) {
        int j = ((tid >> 4) << 8) + (jg << 4) + (tid & 15);
        bias[tid] = b_ih[j] + b_hh[j];
    }
    if (tid < 512) cS[tid] = 0.f;
    __syncthreads();

    const int split = tid >> 6;        // K-split 0..7, kp range [split*16, split*16+16)
    const int wtid  = tid & 63;
    const int tm    = wtid & 7;        // rows 8tm..8tm+7
    const int tb    = wtid >> 3;       // cols 4tb..4tb+3
    float* Gs       = Gst + split * GST_F;

    const int cjh = tid >> 5;          // combine: jh 0..15
    const int cn  = tid & 31;          // combine: batch col
    const size_t gxoff = (size_t)((jg << 4) + cjh) * 256 + (bg << 5) + cn;
    const int jh_g  = (jg << 4) + cjh;
    const size_t hpo = (size_t)(jh_g >> 1) * 512 + (size_t)((bg << 5) + cn) * 2 + (jh_g & 1);

    for (int t = 0; t < NSTEP; ++t) {
        // early gx loads (latency hidden by GEMM)
        const float* gp = g_GX + (size_t)t * 262144 + gxoff;
        float gxi = gp[0];
        float gxf = gp[65536];
        float gxg = gp[131072];
        float gxo = gp[196608];

        // stage h(t-1): already k-pair interleaved in g_Hp
        if (t > 0) {
            const float* hp = g_Hp + (size_t)(t - 1) * 65536 + (size_t)(bg << 5) * 2;
#pragma unroll
            for (int s = 0; s < 4; ++s) {
                int i = tid + s * 512;                    // 2048 float4s total
                int kp = i >> 4, np = i & 15;
                float4 v = ldcg4(hp + (size_t)kp * 512 + (np << 2));
                *reinterpret_cast<float4*>(&hkp[(kp << 6) + (np << 2)]) = v;
            }
        }
        __syncthreads();

        // GEMM: 8x4 cells/thread, k-pair packed FFMA2
        unsigned long long acc[8][4];
#pragma unroll
        for (int r = 0; r < 8; ++r)
#pragma unroll
            for (int c = 0; c < 4; ++c) acc[r][c] = 0ull;

        if (t > 0) {
            const unsigned long long* Wp =
                reinterpret_cast<const unsigned long long*>(Wkp) + (tm << 3);
            const unsigned long long* Hp =
                reinterpret_cast<const unsigned long long*>(hkp) + (tb << 2);
            const int kp0 = split << 4;
#pragma unroll 4
            for (int kp = kp0; kp < kp0 + 16; ++kp) {
                ulonglong2 a01 = *reinterpret_cast<const ulonglong2*>(Wp + (kp << 6));
                ulonglong2 a23 = *reinterpret_cast<const ulonglong2*>(Wp + (kp << 6) + 2);
                ulonglong2 a45 = *reinterpret_cast<const ulonglong2*>(Wp + (kp << 6) + 4);
                ulonglong2 a67 = *reinterpret_cast<const ulonglong2*>(Wp + (kp << 6) + 6);
                ulonglong2 b01 = *reinterpret_cast<const ulonglong2*>(Hp + (kp << 5));
                ulonglong2 b23 = *reinterpret_cast<const ulonglong2*>(Hp + (kp << 5) + 2);
                unsigned long long A[8] = {a01.x, a01.y, a23.x, a23.y,
                                           a45.x, a45.y, a67.x, a67.y};
                unsigned long long B[4] = {b01.x, b01.y, b23.x, b23.y};
#pragma unroll
                for (int r = 0; r < 8; ++r)
#pragma unroll
                    for (int c = 0; c < 4; ++c) fma2(acc[r][c], A[r], B[c]);
            }
        }
        // epilogue: lo+hi per cell -> Gs[m][ld=34] (float2 stores)
#pragma unroll
        for (int r = 0; r < 8; ++r) {
            int m = (tm << 3) + r;
            *reinterpret_cast<float2*>(&Gs[m * GST_LD + (tb << 2)]) =
                make_float2(lohi(acc[r][0]), lohi(acc[r][1]));
            *reinterpret_cast<float2*>(&Gs[m * GST_LD + (tb << 2) + 2]) =
                make_float2(lohi(acc[r][2]), lohi(acc[r][3]));
        }
        __syncthreads();

        // combine: 1 cell/thread; sum 8 K-partials + gx + bias
        {
            float vi = gxi + bias[cjh];
            float vf = gxf + bias[16 + cjh];
            float vg = gxg + bias[32 + cjh];
            float vo = gxo + bias[48 + cjh];
#pragma unroll
            for (int p = 0; p < NSPLIT; ++p) {
                const float* G = Gst + p * GST_F + cn;
                vi += G[(cjh)      * GST_LD];
                vf += G[(16 + cjh) * GST_LD];
                vg += G[(32 + cjh) * GST_LD];
                vo += G[(48 + cjh) * GST_LD];
            }
            float iv = sigf(vi), fv = sigf(vf), gv = tanhfast(vg), ov = sigf(vo);
            int ci = cjh * 32 + cn;
            float cv = fv * cS[ci] + iv * gv;
            cS[ci] = cv;
            g_Hp[(size_t)t * 65536 + hpo] = ov * tanhfast(cv);
        }
        __syncthreads();

        // inter-block barrier (16 jg-blocks sharing this bg)
        if (tid == 0) {
            __threadfence();
            asm volatile("red.release.gpu.global.add.u32 [%0],%1;"
                         :: "l"(&g_bar[bg]), "r"(1u) : "memory");
            unsigned target = (unsigned)(t + 1) << 4;
            unsigned v;
            do {
                asm volatile("ld.acquire.gpu.global.u32 %0,[%1];"
                             : "=r"(v) : "l"(&g_bar[bg]));
            } while (v < target);
        }
        __syncthreads();
    }
}

// ---------------- MDN head ----------------
__device__ __forceinline__ void mdn_gemm(
    const float* __restrict__ At, int ldA, int mTiles, int K,
    const float* __restrict__ Bs, int ldb, float* __restrict__ Cs,
    const float* __restrict__ biasv, bool relu)
{
    for (int tile = threadIdx.x; tile < mTiles * 8; tile += blockDim.x) {
        int tm = tile % mTiles, tb = tile / mTiles;
        int m = tm << 2;
        const float* Ap = At + m;
        const float* Bp = Bs + (tb << 2);
        float acc[4][4];
#pragma unroll
        for (int i = 0; i < 4; ++i)
#pragma unroll
            for (int j = 0; j < 4; ++j) acc[i][j] = 0.f;
#pragma unroll 4
        for (int k = 0; k < K; ++k) {
            float4 a  = *reinterpret_cast<const float4*>(Ap + k * ldA);
            float4 b4 = *reinterpret_cast<const float4*>(Bp + k * ldb);
            float av[4] = {a.x, a.y, a.z, a.w};
            float bv[4] = {b4.x, b4.y, b4.z, b4.w};
#pragma unroll
            for (int i = 0; i < 4; ++i)
#pragma unroll
                for (int j = 0; j < 4; ++j) acc[i][j] = fmaf(av[i], bv[j], acc[i][j]);
        }
#pragma unroll
        for (int i = 0; i < 4; ++i) {
            float bv = biasv[m + i];
            float4 r = make_float4(acc[i][0] + bv, acc[i][1] + bv,
                                   acc[i][2] + bv, acc[i][3] + bv);
            if (relu) { r.x = fmaxf(r.x, 0.f); r.y = fmaxf(r.y, 0.f);
                        r.z = fmaxf(r.z, 0.f); r.w = fmaxf(r.w, 0.f); }
            *reinterpret_cast<float4*>(&Cs[(m + i) * 36 + (tb << 2)]) = r;
        }
    }
}

#define MDN_SMEM_BYTES ((256*32 + 112*36 + 176*36) * 4)

__global__ void __launch_bounds__(256, 2)
mdn_kernel(float* __restrict__ out)
{
    extern __shared__ float sm[];
    float* hT = sm;                 // [256][32], reused as h2 [112][36]
    float* h1 = hT + 256 * 32;      // [112][36]
    float* o3 = h1 + 112 * 36;      // [176][36]

    const int tid = threadIdx.x;
    const int t   = blockIdx.x >> 3;
    const int bg  = blockIdx.x & 7;

    // stage h: de-interleave k-pairs from g_Hp
    const float* hp = g_Hp + (size_t)t * 65536 + (size_t)(bg << 5) * 2;
    for (int i = tid; i < 2048; i += 256) {
        int kp = i >> 4, np = i & 15;
        int n = np << 1;
        float4 v = *reinterpret_cast<const float4*>(hp + (size_t)kp * 512 + (n << 1));
        hT[((kp << 1)    ) * 32 + n    ] = v.x;
        hT[((kp << 1) + 1) * 32 + n    ] = v.y;
        hT[((kp << 1)    ) * 32 + n + 1] = v.z;
        hT[((kp << 1) + 1) * 32 + n + 1] = v.w;
    }
    __syncthreads();

    mdn_gemm(g_W1t, 112, 28, 256, hT, 32, h1, g_b1p, true);
    __syncthreads();
    mdn_gemm(g_W2t, 112, 28, 112, h1, 36, hT, g_b2p, true);   // h2 -> hT (reuse)
    __syncthreads();
    mdn_gemm(g_W3t, 176, 44, 112, hT, 36, o3, g_b3p, false);
    __syncthreads();

    if (tid < 32) {
        int n = tid;
        size_t r = (size_t)((bg << 5) + n) * NSTEP + t;
        float l[5];
        float mx = -1e30f;
#pragma unroll
        for (int k = 0; k < 5; ++k) { l[k] = o3[k * 36 + n]; mx = fmaxf(mx, l[k]); }
        float s = 0.f;
#pragma unroll
        for (int k = 0; k < 5; ++k) { l[k] = __expf(l[k] - mx); s += l[k]; }
        float inv = 1.f / s;
#pragma unroll
        for (int k = 0; k < 5; ++k) out[r * 5 + k] = l[k] * inv;
#pragma unroll
        for (int k = 0; k < 5; ++k)
            out[VARBASE + r * 5 + k] = __expf(o3[(5 + k) * 36 + n]);
    }
    for (int i = tid; i < 5120; i += 256) {
        int n = i / 160, j = i - n * 160;
        size_t r = (size_t)((bg << 5) + n) * NSTEP + t;
        out[MEANBASE + r * 160 + j] = o3[(10 + j) * 36 + n];
    }
}

extern "C" void kernel_launch(void* const* d_in, const int* in_sizes, int n_in,
                              void* d_out, int out_size)
{
    const float* x    = (const float*)d_in[0];
    const float* W_ih = (const float*)d_in[1];
    const float* W_hh = (const float*)d_in[2];
    const float* b_ih = (const float*)d_in[3];
    const float* b_hh = (const float*)d_in[4];
    const float* W1   = (const float*)d_in[5];
    const float* b1   = (const float*)d_in[6];
    const float* W2   = (const float*)d_in[7];
    const float* b2   = (const float*)d_in[8];
    const float* W3   = (const float*)d_in[9];
    const float* b3   = (const float*)d_in[10];
    float* out = (float*)d_out;

    cudaFuncSetAttribute(lstm_kernel, cudaFuncAttributeMaxDynamicSharedMemorySize, LSTM_SMEM_BYTES);
    cudaFuncSetAttribute(mdn_kernel,  cudaFuncAttributeMaxDynamicSharedMemorySize, MDN_SMEM_BYTES);

    prep_w<<<128, 256>>>(W1, b1, W2, b2, W3, b3);
    xproj_kernel<<<dim3(NSTEP, 16, 4), 256>>>(x, W_ih);
    lstm_kernel<<<128, 512, LSTM_SMEM_BYTES>>>(W_hh, b_ih, b_hh);
    mdn_kernel<<<NSTEP * 8, 256, MDN_SMEM_BYTES>>>(out);
}

// round 9
// speedup vs baseline: 1.4074x; 1.4074x over previous
#include <cuda_runtime.h>
#include <cstdint>

#define TDIM   1024
#define NSTEP  1023
#define IN_DIM 35

// output layout: coeff [256][1023][5] | mean [256][1023][5][32] | var [256][1023][5]
#define MEANBASE 1309440
#define VARBASE  43211520

// ---------------- device scratch (allocation-free) ----------------
// h history, k-pair interleaved: g_Hp[t][kp=128][b=256][2] ; elem (h[2kp][b], h[2kp+1][b])
__device__ float g_Hp[(size_t)NSTEP * 256 * 256];
__device__ float g_GX[(size_t)NSTEP * 1024 * 256];  // x-projection, [t][j=1024][b=256]
__device__ float g_W1t[256 * 112];                  // k-major, M padded 100->112
__device__ float g_W2t[112 * 112];
__device__ float g_W3t[112 * 176];                  // M padded 170->176
__device__ float g_b1p[112];
__device__ float g_b2p[112];
__device__ float g_b3p[176];
__device__ unsigned g_bar[8];

// ---------------- prep: barriers + MDN weight transposes ----------------
__global__ void prep_w(const float* __restrict__ W1, const float* __restrict__ b1,
                       const float* __restrict__ W2, const float* __restrict__ b2,
                       const float* __restrict__ W3, const float* __restrict__ b3)
{
    int id = blockIdx.x * blockDim.x + threadIdx.x;
    int stride = gridDim.x * blockDim.x;
    if (id < 8) g_bar[id] = 0u;
    for (int i = id; i < 256 * 112; i += stride) {
        int k = i / 112, m = i - k * 112;
        g_W1t[i] = (m < 100) ? W1[m * 256 + k] : 0.f;
    }
    for (int i = id; i < 112 * 112; i += stride) {
        int k = i / 112, m = i - k * 112;
        g_W2t[i] = (k < 100 && m < 100) ? W2[m * 100 + k] : 0.f;
    }
    for (int i = id; i < 112 * 176; i += stride) {
        int k = i / 176, m = i - k * 176;
        g_W3t[i] = (k < 100 && m < 170) ? W3[m * 100 + k] : 0.f;
    }
    for (int i = id; i < 112; i += stride) {
        g_b1p[i] = (i < 100) ? b1[i] : 0.f;
        g_b2p[i] = (i < 100) ? b2[i] : 0.f;
    }
    for (int i = id; i < 176; i += stride) g_b3p[i] = (i < 170) ? b3[i] : 0.f;
}

// ---------------- x-projection: GX[t][j][b] = sum_c W_ih[j][c] * x[b][t][c] ----------------
__global__ void __launch_bounds__(256)
xproj_kernel(const float* __restrict__ x, const float* __restrict__ W_ih)
{
    __shared__ float Ws[IN_DIM][64];
    __shared__ float xs[IN_DIM][64];
    const int tid = threadIdx.x;
    const int t  = blockIdx.x;
    const int jt = blockIdx.y;
    const int bt = blockIdx.z;

    for (int i = tid; i < 64 * IN_DIM; i += 256) {
        int m = i / IN_DIM, c = i - m * IN_DIM;
        Ws[c][m] = W_ih[(jt * 64 + m) * IN_DIM + c];
    }
    for (int i = tid; i < 64 * IN_DIM; i += 256) {
        int n = i / IN_DIM, c = i - n * IN_DIM;
        xs[c][n] = x[((size_t)(bt * 64 + n) * TDIM + t) * IN_DIM + c];
    }
    __syncthreads();

    const int tm = tid >> 4;
    const int tb = tid & 15;
    float acc[4][4];
#pragma unroll
    for (int i = 0; i < 4; ++i)
#pragma unroll
        for (int j = 0; j < 4; ++j) acc[i][j] = 0.f;
#pragma unroll 5
    for (int c = 0; c < IN_DIM; ++c) {
        float4 a  = *reinterpret_cast<const float4*>(&Ws[c][tm << 2]);
        float4 b4 = *reinterpret_cast<const float4*>(&xs[c][tb << 2]);
        float av[4] = {a.x, a.y, a.z, a.w};
        float bv[4] = {b4.x, b4.y, b4.z, b4.w};
#pragma unroll
        for (int i = 0; i < 4; ++i)
#pragma unroll
            for (int j = 0; j < 4; ++j) acc[i][j] = fmaf(av[i], bv[j], acc[i][j]);
    }
    float* dst = g_GX + (size_t)t * 262144 + (size_t)(jt * 64 + (tm << 2)) * 256
                 + bt * 64 + (tb << 2);
#pragma unroll
    for (int i = 0; i < 4; ++i)
        *reinterpret_cast<float4*>(dst + (size_t)i * 256) =
            make_float4(acc[i][0], acc[i][1], acc[i][2], acc[i][3]);
}

__device__ __forceinline__ float sigf(float v)     { return 1.f / (1.f + __expf(-v)); }
__device__ __forceinline__ float tanhfast(float v) { return 1.f - 2.f / (__expf(2.f * v) + 1.f); }

__device__ __forceinline__ float4 ldcg4(const float* p) {
    float4 v;
    asm volatile("ld.global.cg.v4.f32 {%0,%1,%2,%3},[%4];"
                 : "=f"(v.x), "=f"(v.y), "=f"(v.z), "=f"(v.w) : "l"(p));
    return v;
}
__device__ __forceinline__ void fma2(unsigned long long& d,
                                     unsigned long long a, unsigned long long b) {
    asm("fma.rn.f32x2 %0, %1, %2, %0;" : "+l"(d) : "l"(a), "l"(b));
}
__device__ __forceinline__ float lohi(unsigned long long v) {
    return __uint_as_float((unsigned)v) + __uint_as_float((unsigned)(v >> 32));
}

// ---------------- persistent LSTM ----------------
// grid 128: jg = blockIdx>>3 (16 hid-tiles of 16), bg = blockIdx&7 (8 batch-tiles of 32)
// 512 threads = 4 K-splits x 128; thread tile = 4 rows x 4 cols, k-pair FFMA2.
#define WKP_F  16384      // [kp=128][m=64] u64 pairs (floats x2)
#define HKP_F  8192       // [kp=128][n=32] u64 pairs
#define GST_LD 34
#define GST_F  (64 * GST_LD)
#define NSPLIT 4
#define LSTM_SMEM_BYTES ((WKP_F + HKP_F + NSPLIT*GST_F + 64 + 512 + 32) * 4)

__global__ void __launch_bounds__(512, 1)
lstm_kernel(const float* __restrict__ W_hh,
            const float* __restrict__ b_ih, const float* __restrict__ b_hh)
{
    extern __shared__ float sm[];
    float* Wkp  = sm;                  // k-pair interleaved weights
    float* hkp  = Wkp + WKP_F;         // k-pair interleaved h
    float* Gst  = hkp + HKP_F;         // 4 x [m=64][ld=34]
    float* bias = Gst + NSPLIT * GST_F;
    float* cS   = bias + 64;           // [16][32]

    const int tid = threadIdx.x;
    const int bg  = blockIdx.x & 7;
    const int jg  = blockIdx.x >> 3;

    // one-time weight staging: Wkp[kp][m] = (W[j][2kp], W[j][2kp+1])
    for (int i = tid; i < 128 * 64; i += 512) {
        int kp = i >> 6, m = i & 63;
        int j  = ((m >> 4) << 8) + (jg << 4) + (m & 15);   // gate*256 + jg*16 + jh
        float2 w = *reinterpret_cast<const float2*>(&W_hh[j * 256 + (kp << 1)]);
        *reinterpret_cast<float2*>(&Wkp[i << 1]) = w;
    }
    if (tid < 64) {
        int j = ((tid >> 4) << 8) + (jg << 4) + (tid & 15);
        bias[tid] = b_ih[j] + b_hh[j];
    }
    if (tid < 512) cS[tid] = 0.f;
    __syncthreads();

    const int split = tid >> 7;        // K-split 0..3, kp range [split*32, split*32+32)
    const int wtid  = tid & 127;
    const int tm    = wtid & 15;       // rows 4tm..4tm+3
    const int tb    = wtid >> 4;       // cols 4tb..4tb+3
    float* Gs       = Gst + split * GST_F;

    const int cjh = tid >> 5;          // combine: jh 0..15
    const int cn  = tid & 31;          // combine: batch col
    const size_t gxoff = (size_t)((jg << 4) + cjh) * 256 + (bg << 5) + cn;
    const int jh_g  = (jg << 4) + cjh;
    const size_t hpo = (size_t)(jh_g >> 1) * 512 + (size_t)((bg << 5) + cn) * 2 + (jh_g & 1);

    for (int t = 0; t < NSTEP; ++t) {
        // early gx loads (latency hidden by GEMM)
        const float* gp = g_GX + (size_t)t * 262144 + gxoff;
        float gxi = gp[0];
        float gxf = gp[65536];
        float gxg = gp[131072];
        float gxo = gp[196608];

        // stage h(t-1): already k-pair interleaved in g_Hp
        if (t > 0) {
            const float* hp = g_Hp + (size_t)(t - 1) * 65536 + (size_t)(bg << 5) * 2;
#pragma unroll
            for (int s = 0; s < 4; ++s) {
                int i = tid + s * 512;                    // 2048 float4s total
                int kp = i >> 4, np = i & 15;
                float4 v = ldcg4(hp + (size_t)kp * 512 + (np << 2));
                *reinterpret_cast<float4*>(&hkp[(kp << 6) + (np << 2)]) = v;
            }
        }
        __syncthreads();

        // GEMM: 4x4 cells/thread, k-pair packed FFMA2
        unsigned long long acc[4][4];
#pragma unroll
        for (int r = 0; r < 4; ++r)
#pragma unroll
            for (int c = 0; c < 4; ++c) acc[r][c] = 0ull;

        if (t > 0) {
            const unsigned long long* Wp =
                reinterpret_cast<const unsigned long long*>(Wkp) + (tm << 2);
            const unsigned long long* Hp =
                reinterpret_cast<const unsigned long long*>(hkp) + (tb << 2);
            const int kp0 = split << 5;
#pragma unroll 8
            for (int kp = kp0; kp < kp0 + 32; ++kp) {
                ulonglong2 a01 = *reinterpret_cast<const ulonglong2*>(Wp + (kp << 6));
                ulonglong2 a23 = *reinterpret_cast<const ulonglong2*>(Wp + (kp << 6) + 2);
                ulonglong2 b01 = *reinterpret_cast<const ulonglong2*>(Hp + (kp << 5));
                ulonglong2 b23 = *reinterpret_cast<const ulonglong2*>(Hp + (kp << 5) + 2);
                fma2(acc[0][0], a01.x, b01.x); fma2(acc[1][0], a01.y, b01.x);
                fma2(acc[2][0], a23.x, b01.x); fma2(acc[3][0], a23.y, b01.x);
                fma2(acc[0][1], a01.x, b01.y); fma2(acc[1][1], a01.y, b01.y);
                fma2(acc[2][1], a23.x, b01.y); fma2(acc[3][1], a23.y, b01.y);
                fma2(acc[0][2], a01.x, b23.x); fma2(acc[1][2], a01.y, b23.x);
                fma2(acc[2][2], a23.x, b23.x); fma2(acc[3][2], a23.y, b23.x);
                fma2(acc[0][3], a01.x, b23.y); fma2(acc[1][3], a01.y, b23.y);
                fma2(acc[2][3], a23.x, b23.y); fma2(acc[3][3], a23.y, b23.y);
            }
        }
        // epilogue: lo+hi per cell -> Gs[m][ld=34]
#pragma unroll
        for (int r = 0; r < 4; ++r) {
            int m = (tm << 2) + r;
            *reinterpret_cast<float2*>(&Gs[m * GST_LD + (tb << 2)]) =
                make_float2(lohi(acc[r][0]), lohi(acc[r][1]));
            *reinterpret_cast<float2*>(&Gs[m * GST_LD + (tb << 2) + 2]) =
                make_float2(lohi(acc[r][2]), lohi(acc[r][3]));
        }
        __syncthreads();

        // combine: 1 cell/thread; sum 4 K-partials + gx + bias
        {
            float vi = gxi + bias[cjh];
            float vf = gxf + bias[16 + cjh];
            float vg = gxg + bias[32 + cjh];
            float vo = gxo + bias[48 + cjh];
#pragma unroll
            for (int p = 0; p < NSPLIT; ++p) {
                const float* G = Gst + p * GST_F + cn;
                vi += G[(cjh)      * GST_LD];
                vf += G[(16 + cjh) * GST_LD];
                vg += G[(32 + cjh) * GST_LD];
                vo += G[(48 + cjh) * GST_LD];
            }
            float iv = sigf(vi), fv = sigf(vf), gv = tanhfast(vg), ov = sigf(vo);
            int ci = cjh * 32 + cn;
            float cv = fv * cS[ci] + iv * gv;
            cS[ci] = cv;
            g_Hp[(size_t)t * 65536 + hpo] = ov * tanhfast(cv);
        }
        __syncthreads();

        // inter-block barrier (16 jg-blocks sharing this bg)
        if (tid == 0) {
            __threadfence();
            asm volatile("red.release.gpu.global.add.u32 [%0],%1;"
                         :: "l"(&g_bar[bg]), "r"(1u) : "memory");
            unsigned target = (unsigned)(t + 1) << 4;
            unsigned v;
            do {
                asm volatile("ld.acquire.gpu.global.u32 %0,[%1];"
                             : "=r"(v) : "l"(&g_bar[bg]));
            } while (v < target);
        }
        __syncthreads();
    }
}

// ---------------- MDN head ----------------
__device__ __forceinline__ void mdn_gemm(
    const float* __restrict__ At, int ldA, int mTiles, int K,
    const float* __restrict__ Bs, int ldb, float* __restrict__ Cs,
    const float* __restrict__ biasv, bool relu)
{
    for (int tile = threadIdx.x; tile < mTiles * 8; tile += blockDim.x) {
        int tm = tile % mTiles, tb = tile / mTiles;
        int m = tm << 2;
        const float* Ap = At + m;
        const float* Bp = Bs + (tb << 2);
        float acc[4][4];
#pragma unroll
        for (int i = 0; i < 4; ++i)
#pragma unroll
            for (int j = 0; j < 4; ++j) acc[i][j] = 0.f;
#pragma unroll 4
        for (int k = 0; k < K; ++k) {
            float4 a  = *reinterpret_cast<const float4*>(Ap + k * ldA);
            float4 b4 = *reinterpret_cast<const float4*>(Bp + k * ldb);
            float av[4] = {a.x, a.y, a.z, a.w};
            float bv[4] = {b4.x, b4.y, b4.z, b4.w};
#pragma unroll
            for (int i = 0; i < 4; ++i)
#pragma unroll
                for (int j = 0; j < 4; ++j) acc[i][j] = fmaf(av[i], bv[j], acc[i][j]);
        }
#pragma unroll
        for (int i = 0; i < 4; ++i) {
            float bv = biasv[m + i];
            float4 r = make_float4(acc[i][0] + bv, acc[i][1] + bv,
                                   acc[i][2] + bv, acc[i][3] + bv);
            if (relu) { r.x = fmaxf(r.x, 0.f); r.y = fmaxf(r.y, 0.f);
                        r.z = fmaxf(r.z, 0.f); r.w = fmaxf(r.w, 0.f); }
            *reinterpret_cast<float4*>(&Cs[(m + i) * 36 + (tb << 2)]) = r;
        }
    }
}

#define MDN_SMEM_BYTES ((256*32 + 112*36 + 176*36) * 4)

__global__ void __launch_bounds__(256, 2)
mdn_kernel(float* __restrict__ out)
{
    extern __shared__ float sm[];
    float* hT = sm;                 // [256][32], reused as h2 [112][36]
    float* h1 = hT + 256 * 32;      // [112][36]
    float* o3 = h1 + 112 * 36;      // [176][36]

    const int tid = threadIdx.x;
    const int t   = blockIdx.x >> 3;
    const int bg  = blockIdx.x & 7;

    // stage h: de-interleave k-pairs from g_Hp
    const float* hp = g_Hp + (size_t)t * 65536 + (size_t)(bg << 5) * 2;
    for (int i = tid; i < 2048; i += 256) {
        int kp = i >> 4, np = i & 15;
        int n = np << 1;
        float4 v = *reinterpret_cast<const float4*>(hp + (size_t)kp * 512 + (n << 1));
        hT[((kp << 1)    ) * 32 + n    ] = v.x;
        hT[((kp << 1) + 1) * 32 + n    ] = v.y;
        hT[((kp << 1)    ) * 32 + n + 1] = v.z;
        hT[((kp << 1) + 1) * 32 + n + 1] = v.w;
    }
    __syncthreads();

    mdn_gemm(g_W1t, 112, 28, 256, hT, 32, h1, g_b1p, true);
    __syncthreads();
    mdn_gemm(g_W2t, 112, 28, 112, h1, 36, hT, g_b2p, true);   // h2 -> hT (reuse)
    __syncthreads();
    mdn_gemm(g_W3t, 176, 44, 112, hT, 36, o3, g_b3p, false);
    __syncthreads();

    if (tid < 32) {
        int n = tid;
        size_t r = (size_t)((bg << 5) + n) * NSTEP + t;
        float l[5];
        float mx = -1e30f;
#pragma unroll
        for (int k = 0; k < 5; ++k) { l[k] = o3[k * 36 + n]; mx = fmaxf(mx, l[k]); }
        float s = 0.f;
#pragma unroll
        for (int k = 0; k < 5; ++k) { l[k] = __expf(l[k] - mx); s += l[k]; }
        float inv = 1.f / s;
#pragma unroll
        for (int k = 0; k < 5; ++k) out[r * 5 + k] = l[k] * inv;
#pragma unroll
        for (int k = 0; k < 5; ++k)
            out[VARBASE + r * 5 + k] = __expf(o3[(5 + k) * 36 + n]);
    }
    for (int i = tid; i < 5120; i += 256) {
        int n = i / 160, j = i - n * 160;
        size_t r = (size_t)((bg << 5) + n) * NSTEP + t;
        out[MEANBASE + r * 160 + j] = o3[(10 + j) * 36 + n];
    }
}

extern "C" void kernel_launch(void* const* d_in, const int* in_sizes, int n_in,
                              void* d_out, int out_size)
{
    const float* x    = (const float*)d_in[0];
    const float* W_ih = (const float*)d_in[1];
    const float* W_hh = (const float*)d_in[2];
    const float* b_ih = (const float*)d_in[3];
    const float* b_hh = (const float*)d_in[4];
    const float* W1   = (const float*)d_in[5];
    const float* b1   = (const float*)d_in[6];
    const float* W2   = (const float*)d_in[7];
    const float* b2   = (const float*)d_in[8];
    const float* W3   = (const float*)d_in[9];
    const float* b3   = (const float*)d_in[10];
    float* out = (float*)d_out;

    cudaFuncSetAttribute(lstm_kernel, cudaFuncAttributeMaxDynamicSharedMemorySize, LSTM_SMEM_BYTES);
    cudaFuncSetAttribute(mdn_kernel,  cudaFuncAttributeMaxDynamicSharedMemorySize, MDN_SMEM_BYTES);

    prep_w<<<128, 256>>>(W1, b1, W2, b2, W3, b3);
    xproj_kernel<<<dim3(NSTEP, 16, 4), 256>>>(x, W_ih);
    lstm_kernel<<<128, 512, LSTM_SMEM_BYTES>>>(W_hh, b_ih, b_hh);
    mdn_kernel<<<NSTEP * 8, 256, MDN_SMEM_BYTES>>>(out);
}

// round 10
// speedup vs baseline: 1.6046x; 1.1402x over previous
#include <cuda_runtime.h>
#include <cstdint>

#define TDIM   1024
#define NSTEP  1023
#define IN_DIM 35

// output layout: coeff [256][1023][5] | mean [256][1023][5][32] | var [256][1023][5]
#define MEANBASE 1309440
#define VARBASE  43211520

// ---------------- device scratch (allocation-free) ----------------
// h history, k-pair interleaved: g_Hp[t][kp=128][b=256][2] ; elem (h[2kp][b], h[2kp+1][b])
__device__ float g_Hp[(size_t)NSTEP * 256 * 256];
__device__ float g_GX[(size_t)NSTEP * 1024 * 256];  // x-projection, [t][j=1024][b=256]
__device__ float g_W1t[256 * 112];                  // k-major, M padded 100->112
__device__ float g_W2t[112 * 112];
__device__ float g_W3t[112 * 176];                  // M padded 170->176
__device__ float g_b1p[112];
__device__ float g_b2p[112];
__device__ float g_b3p[176];
__device__ unsigned g_bar[8];

// ---------------- prep: barriers + MDN weight transposes ----------------
__global__ void prep_w(const float* __restrict__ W1, const float* __restrict__ b1,
                       const float* __restrict__ W2, const float* __restrict__ b2,
                       const float* __restrict__ W3, const float* __restrict__ b3)
{
    int id = blockIdx.x * blockDim.x + threadIdx.x;
    int stride = gridDim.x * blockDim.x;
    if (id < 8) g_bar[id] = 0u;
    for (int i = id; i < 256 * 112; i += stride) {
        int k = i / 112, m = i - k * 112;
        g_W1t[i] = (m < 100) ? W1[m * 256 + k] : 0.f;
    }
    for (int i = id; i < 112 * 112; i += stride) {
        int k = i / 112, m = i - k * 112;
        g_W2t[i] = (k < 100 && m < 100) ? W2[m * 100 + k] : 0.f;
    }
    for (int i = id; i < 112 * 176; i += stride) {
        int k = i / 176, m = i - k * 176;
        g_W3t[i] = (k < 100 && m < 170) ? W3[m * 100 + k] : 0.f;
    }
    for (int i = id; i < 112; i += stride) {
        g_b1p[i] = (i < 100) ? b1[i] : 0.f;
        g_b2p[i] = (i < 100) ? b2[i] : 0.f;
    }
    for (int i = id; i < 176; i += stride) g_b3p[i] = (i < 170) ? b3[i] : 0.f;
}

// ---------------- x-projection: GX[t][j][b] = sum_c W_ih[j][c] * x[b][t][c] ----------------
__global__ void __launch_bounds__(256)
xproj_kernel(const float* __restrict__ x, const float* __restrict__ W_ih)
{
    __shared__ float Ws[IN_DIM][64];
    __shared__ float xs[IN_DIM][64];
    const int tid = threadIdx.x;
    const int t  = blockIdx.x;
    const int jt = blockIdx.y;
    const int bt = blockIdx.z;

    for (int i = tid; i < 64 * IN_DIM; i += 256) {
        int m = i / IN_DIM, c = i - m * IN_DIM;
        Ws[c][m] = W_ih[(jt * 64 + m) * IN_DIM + c];
    }
    for (int i = tid; i < 64 * IN_DIM; i += 256) {
        int n = i / IN_DIM, c = i - n * IN_DIM;
        xs[c][n] = x[((size_t)(bt * 64 + n) * TDIM + t) * IN_DIM + c];
    }
    __syncthreads();

    const int tm = tid >> 4;
    const int tb = tid & 15;
    float acc[4][4];
#pragma unroll
    for (int i = 0; i < 4; ++i)
#pragma unroll
        for (int j = 0; j < 4; ++j) acc[i][j] = 0.f;
#pragma unroll 5
    for (int c = 0; c < IN_DIM; ++c) {
        float4 a  = *reinterpret_cast<const float4*>(&Ws[c][tm << 2]);
        float4 b4 = *reinterpret_cast<const float4*>(&xs[c][tb << 2]);
        float av[4] = {a.x, a.y, a.z, a.w};
        float bv[4] = {b4.x, b4.y, b4.z, b4.w};
#pragma unroll
        for (int i = 0; i < 4; ++i)
#pragma unroll
            for (int j = 0; j < 4; ++j) acc[i][j] = fmaf(av[i], bv[j], acc[i][j]);
    }
    float* dst = g_GX + (size_t)t * 262144 + (size_t)(jt * 64 + (tm << 2)) * 256
                 + bt * 64 + (tb << 2);
#pragma unroll
    for (int i = 0; i < 4; ++i)
        *reinterpret_cast<float4*>(dst + (size_t)i * 256) =
            make_float4(acc[i][0], acc[i][1], acc[i][2], acc[i][3]);
}

__device__ __forceinline__ float sigf(float v)     { return 1.f / (1.f + __expf(-v)); }
__device__ __forceinline__ float tanhfast(float v) { return 1.f - 2.f / (__expf(2.f * v) + 1.f); }

__device__ __forceinline__ float4 ldcg4(const float* p) {
    float4 v;
    asm volatile("ld.global.cg.v4.f32 {%0,%1,%2,%3},[%4];"
                 : "=f"(v.x), "=f"(v.y), "=f"(v.z), "=f"(v.w) : "l"(p));
    return v;
}
__device__ __forceinline__ float ldcg1(const float* p) {
    float v;
    asm volatile("ld.global.cg.f32 %0,[%1];" : "=f"(v) : "l"(p));
    return v;
}
__device__ __forceinline__ void fma2(unsigned long long& d,
                                     unsigned long long a, unsigned long long b) {
    asm("fma.rn.f32x2 %0, %1, %2, %0;" : "+l"(d) : "l"(a), "l"(b));
}
__device__ __forceinline__ float lohi(unsigned long long v) {
    return __uint_as_float((unsigned)v) + __uint_as_float((unsigned)(v >> 32));
}

// ---------------- persistent LSTM ----------------
// grid 148 (blocks >=128 exit): jg = blockIdx>>3 (16 hid-tiles), bg = blockIdx&7 (8 batch-tiles)
// 512 threads = 16 warps = 4 n-tiles x 4 k-splits; lane = m-pair. Conflict-free LDS.
#define WKP_U  8192                // u64 [kp=128][m=64]
#define HKP_U  4096                // u64 [kp=128][b=32]
#define GST_LD 66                  // u64 row stride (528B, 16B-aligned)
#define GST_U  (32 * GST_LD)       // u64 per split buffer
#define NSPLIT 4
#define LSTM_SMEM_BYTES ((WKP_U + HKP_U + NSPLIT * GST_U) * 8 + (64 + 512 + 32) * 4)

__global__ void __launch_bounds__(512, 1)
lstm_kernel(const float* __restrict__ W_hh,
            const float* __restrict__ b_ih, const float* __restrict__ b_hh)
{
    extern __shared__ unsigned long long smu[];
    unsigned long long* Wkp  = smu;                 // [kp][m] k-pair packed
    unsigned long long* hkp  = Wkp + WKP_U;         // [kp][b] k-pair packed
    unsigned long long* Gst  = hkp + HKP_U;         // 4 x u64 [n=32][m pad 66]
    float* bias = reinterpret_cast<float*>(Gst + NSPLIT * GST_U);
    float* cS   = bias + 64;                        // [16][32]

    const int tid = threadIdx.x;
    if (blockIdx.x >= 128) return;                  // grid padded to 148
    const int bg  = blockIdx.x & 7;
    const int jg  = blockIdx.x >> 3;

    // one-time weight staging: Wkp[kp][m] = (W[j][2kp], W[j][2kp+1]) as u64
    for (int i = tid; i < 128 * 64; i += 512) {
        int kp = i >> 6, m = i & 63;
        int j  = ((m >> 4) << 8) + (jg << 4) + (m & 15);   // gate*256 + jg*16 + jh
        float2 w = *reinterpret_cast<const float2*>(&W_hh[j * 256 + (kp << 1)]);
        *reinterpret_cast<float2*>(&Wkp[i]) = w;
    }
    if (tid < 64) {
        int j = ((tid >> 4) << 8) + (jg << 4) + (tid & 15);
        bias[tid] = b_ih[j] + b_hh[j];
    }
    if (tid < 512) cS[tid] = 0.f;
    __syncthreads();

    const int warp = tid >> 5;
    const int lane = tid & 31;         // m-pair {2*lane, 2*lane+1}
    const int ks   = warp & 3;         // k-split 0..3: kp in [ks*32, ks*32+32)
    const int nt   = warp >> 2;        // n-tile 0..3: n in [nt*8, nt*8+8)
    unsigned long long* Gs = Gst + ks * GST_U;

    const int cjh = tid >> 5;          // combine: jh 0..15
    const int cn  = tid & 31;          // combine: batch col
    const size_t gxoff = (size_t)((jg << 4) + cjh) * 256 + (bg << 5) + cn;
    const int jh_g  = (jg << 4) + cjh;
    const size_t hpo = (size_t)(jh_g >> 1) * 512 + (size_t)((bg << 5) + cn) * 2 + (jh_g & 1);

    for (int t = 0; t < NSTEP; ++t) {
        // early gx loads (asm volatile: cannot be sunk to combine)
        const float* gp = g_GX + (size_t)t * 262144 + gxoff;
        float gxi = ldcg1(gp);
        float gxf = ldcg1(gp + 65536);
        float gxg = ldcg1(gp + 131072);
        float gxo = ldcg1(gp + 196608);

        // stage h(t-1): g_Hp is already k-pair interleaved [kp][b][2]
        if (t > 0) {
            const float* hp = g_Hp + (size_t)(t - 1) * 65536 + (size_t)(bg << 5) * 2;
            float* hkf = reinterpret_cast<float*>(hkp);
#pragma unroll
            for (int s = 0; s < 4; ++s) {
                int i = tid + s * 512;                    // 2048 float4s total
                int kp = i >> 4, np = i & 15;
                float4 v = ldcg4(hp + (size_t)kp * 512 + (np << 2));
                *reinterpret_cast<float4*>(&hkf[(kp << 6) + (np << 2)]) = v;
            }
        }
        __syncthreads();

        // GEMM: lane owns m-pair (conflict-free A row reads), warp owns (nt, ks)
        unsigned long long acc[2][8];
#pragma unroll
        for (int r = 0; r < 2; ++r)
#pragma unroll
            for (int c = 0; c < 8; ++c) acc[r][c] = 0ull;

        if (t > 0) {
            const int kp0 = ks << 5;
#pragma unroll 4
            for (int kp = kp0; kp < kp0 + 32; ++kp) {
                // A: 32 lanes read consecutive 16B chunks of the 512B row -> no conflicts
                ulonglong2 a = *reinterpret_cast<const ulonglong2*>(&Wkp[(kp << 6) + (lane << 1)]);
                // B: all lanes same address -> broadcast
                const unsigned long long* hb = hkp + (kp << 5) + (nt << 3);
                ulonglong2 b01 = *reinterpret_cast<const ulonglong2*>(hb);
                ulonglong2 b23 = *reinterpret_cast<const ulonglong2*>(hb + 2);
                ulonglong2 b45 = *reinterpret_cast<const ulonglong2*>(hb + 4);
                ulonglong2 b67 = *reinterpret_cast<const ulonglong2*>(hb + 6);
                fma2(acc[0][0], a.x, b01.x); fma2(acc[1][0], a.y, b01.x);
                fma2(acc[0][1], a.x, b01.y); fma2(acc[1][1], a.y, b01.y);
                fma2(acc[0][2], a.x, b23.x); fma2(acc[1][2], a.y, b23.x);
                fma2(acc[0][3], a.x, b23.y); fma2(acc[1][3], a.y, b23.y);
                fma2(acc[0][4], a.x, b45.x); fma2(acc[1][4], a.y, b45.x);
                fma2(acc[0][5], a.x, b45.y); fma2(acc[1][5], a.y, b45.y);
                fma2(acc[0][6], a.x, b67.x); fma2(acc[1][6], a.y, b67.x);
                fma2(acc[0][7], a.x, b67.y); fma2(acc[1][7], a.y, b67.y);
            }
        }
        // epilogue: raw u64 (even/odd k sums) -> Gst[n][m], 16B-aligned, conflict-free
#pragma unroll
        for (int c = 0; c < 8; ++c) {
            ulonglong2 v; v.x = acc[0][c]; v.y = acc[1][c];
            *reinterpret_cast<ulonglong2*>(&Gs[((nt << 3) + c) * GST_LD + (lane << 1)]) = v;
        }
        __syncthreads();

        // combine: 1 cell/thread; fold lo+hi of 4 split-partials + gx + bias
        {
            float vi = gxi + bias[cjh];
            float vf = gxf + bias[16 + cjh];
            float vg = gxg + bias[32 + cjh];
            float vo = gxo + bias[48 + cjh];
#pragma unroll
            for (int p = 0; p < NSPLIT; ++p) {
                const unsigned long long* G = Gst + p * GST_U + (size_t)cn * GST_LD;
                vi += lohi(G[cjh]);
                vf += lohi(G[16 + cjh]);
                vg += lohi(G[32 + cjh]);
                vo += lohi(G[48 + cjh]);
            }
            float iv = sigf(vi), fv = sigf(vf), gv = tanhfast(vg), ov = sigf(vo);
            int ci = cjh * 32 + cn;
            float cv = fv * cS[ci] + iv * gv;
            cS[ci] = cv;
            g_Hp[(size_t)t * 65536 + hpo] = ov * tanhfast(cv);
        }
        __syncthreads();

        // inter-block barrier (16 jg-blocks sharing this bg)
        if (tid == 0) {
            __threadfence();
            asm volatile("red.release.gpu.global.add.u32 [%0],%1;"
                         :: "l"(&g_bar[bg]), "r"(1u) : "memory");
            unsigned target = (unsigned)(t + 1) << 4;
            unsigned v;
            for (;;) {
                asm volatile("ld.acquire.gpu.global.u32 %0,[%1];"
                             : "=r"(v) : "l"(&g_bar[bg]));
                if (v >= target) break;
                __nanosleep(32);
            }
        }
        __syncthreads();
    }
}

// ---------------- MDN head ----------------
__device__ __forceinline__ void mdn_gemm(
    const float* __restrict__ At, int ldA, int mTiles, int K,
    const float* __restrict__ Bs, int ldb, float* __restrict__ Cs,
    const float* __restrict__ biasv, bool relu)
{
    for (int tile = threadIdx.x; tile < mTiles * 8; tile += blockDim.x) {
        int tm = tile % mTiles, tb = tile / mTiles;
        int m = tm << 2;
        const float* Ap = At + m;
        const float* Bp = Bs + (tb << 2);
        float acc[4][4];
#pragma unroll
        for (int i = 0; i < 4; ++i)
#pragma unroll
            for (int j = 0; j < 4; ++j) acc[i][j] = 0.f;
#pragma unroll 4
        for (int k = 0; k < K; ++k) {
            float4 a  = *reinterpret_cast<const float4*>(Ap + k * ldA);
            float4 b4 = *reinterpret_cast<const float4*>(Bp + k * ldb);
            float av[4] = {a.x, a.y, a.z, a.w};
            float bv[4] = {b4.x, b4.y, b4.z, b4.w};
#pragma unroll
            for (int i = 0; i < 4; ++i)
#pragma unroll
                for (int j = 0; j < 4; ++j) acc[i][j] = fmaf(av[i], bv[j], acc[i][j]);
        }
#pragma unroll
        for (int i = 0; i < 4; ++i) {
            float bv = biasv[m + i];
            float4 r = make_float4(acc[i][0] + bv, acc[i][1] + bv,
                                   acc[i][2] + bv, acc[i][3] + bv);
            if (relu) { r.x = fmaxf(r.x, 0.f); r.y = fmaxf(r.y, 0.f);
                        r.z = fmaxf(r.z, 0.f); r.w = fmaxf(r.w, 0.f); }
            *reinterpret_cast<float4*>(&Cs[(m + i) * 36 + (tb << 2)]) = r;
        }
    }
}

#define MDN_SMEM_BYTES ((256*32 + 112*36 + 176*36) * 4)

__global__ void __launch_bounds__(256, 2)
mdn_kernel(float* __restrict__ out)
{
    extern __shared__ float sm[];
    float* hT = sm;                 // [256][32], reused as h2 [112][36]
    float* h1 = hT + 256 * 32;      // [112][36]
    float* o3 = h1 + 112 * 36;      // [176][36]

    const int tid = threadIdx.x;
    const int t   = blockIdx.x >> 3;
    const int bg  = blockIdx.x & 7;

    // stage h: de-interleave k-pairs from g_Hp
    const float* hp = g_Hp + (size_t)t * 65536 + (size_t)(bg << 5) * 2;
    for (int i = tid; i < 2048; i += 256) {
        int kp = i >> 4, np = i & 15;
        int n = np << 1;
        float4 v = *reinterpret_cast<const float4*>(hp + (size_t)kp * 512 + (n << 1));
        hT[((kp << 1)    ) * 32 + n    ] = v.x;
        hT[((kp << 1) + 1) * 32 + n    ] = v.y;
        hT[((kp << 1)    ) * 32 + n + 1] = v.z;
        hT[((kp << 1) + 1) * 32 + n + 1] = v.w;
    }
    __syncthreads();

    mdn_gemm(g_W1t, 112, 28, 256, hT, 32, h1, g_b1p, true);
    __syncthreads();
    mdn_gemm(g_W2t, 112, 28, 112, h1, 36, hT, g_b2p, true);   // h2 -> hT (reuse)
    __syncthreads();
    mdn_gemm(g_W3t, 176, 44, 112, hT, 36, o3, g_b3p, false);
    __syncthreads();

    if (tid < 32) {
        int n = tid;
        size_t r = (size_t)((bg << 5) + n) * NSTEP + t;
        float l[5];
        float mx = -1e30f;
#pragma unroll
        for (int k = 0; k < 5; ++k) { l[k] = o3[k * 36 + n]; mx = fmaxf(mx, l[k]); }
        float s = 0.f;
#pragma unroll
        for (int k = 0; k < 5; ++k) { l[k] = __expf(l[k] - mx); s += l[k]; }
        float inv = 1.f / s;
#pragma unroll
        for (int k = 0; k < 5; ++k) out[r * 5 + k] = l[k] * inv;
#pragma unroll
        for (int k = 0; k < 5; ++k)
            out[VARBASE + r * 5 + k] = __expf(o3[(5 + k) * 36 + n]);
    }
    for (int i = tid; i < 5120; i += 256) {
        int n = i / 160, j = i - n * 160;
        size_t r = (size_t)((bg << 5) + n) * NSTEP + t;
        out[MEANBASE + r * 160 + j] = o3[(10 + j) * 36 + n];
    }
}

extern "C" void kernel_launch(void* const* d_in, const int* in_sizes, int n_in,
                              void* d_out, int out_size)
{
    const float* x    = (const float*)d_in[0];
    const float* W_ih = (const float*)d_in[1];
    const float* W_hh = (const float*)d_in[2];
    const float* b_ih = (const float*)d_in[3];
    const float* b_hh = (const float*)d_in[4];
    const float* W1   = (const float*)d_in[5];
    const float* b1   = (const float*)d_in[6];
    const float* W2   = (const float*)d_in[7];
    const float* b2   = (const float*)d_in[8];
    const float* W3   = (const float*)d_in[9];
    const float* b3   = (const float*)d_in[10];
    float* out = (float*)d_out;

    cudaFuncSetAttribute(lstm_kernel, cudaFuncAttributeMaxDynamicSharedMemorySize, LSTM_SMEM_BYTES);
    cudaFuncSetAttribute(mdn_kernel,  cudaFuncAttributeMaxDynamicSharedMemorySize, MDN_SMEM_BYTES);

    prep_w<<<128, 256>>>(W1, b1, W2, b2, W3, b3);
    xproj_kernel<<<dim3(NSTEP, 16, 4), 256>>>(x, W_ih);
    lstm_kernel<<<148, 512, LSTM_SMEM_BYTES>>>(W_hh, b_ih, b_hh);
    mdn_kernel<<<NSTEP * 8, 256, MDN_SMEM_BYTES>>>(out);
}

// round 12
// speedup vs baseline: 2.0695x; 1.2897x over previous
#include <cuda_runtime.h>
#include <cuda_bf16.h>
#include <cstdint>

#define TDIM   1024
#define NSTEP  1023
#define IN_DIM 35

// output layout: coeff [256][1023][5] | mean [256][1023][5][32] | var [256][1023][5]
#define MEANBASE 1309440
#define VARBASE  43211520

// ---------------- device scratch (allocation-free) ----------------
__device__ float g_H[(size_t)NSTEP * 256 * 256];    // h history, [t][k=256][b=256]
__device__ float g_GX[(size_t)NSTEP * 1024 * 256];  // x-projection, [t][j=1024][b=256]
__device__ float g_W1t[256 * 112];
__device__ float g_W2t[112 * 112];
__device__ float g_W3t[112 * 176];
__device__ float g_b1p[112];
__device__ float g_b2p[112];
__device__ float g_b3p[176];
__device__ unsigned g_bar[8];

// ---------------- prep ----------------
__global__ void prep_w(const float* __restrict__ W1, const float* __restrict__ b1,
                       const float* __restrict__ W2, const float* __restrict__ b2,
                       const float* __restrict__ W3, const float* __restrict__ b3)
{
    int id = blockIdx.x * blockDim.x + threadIdx.x;
    int stride = gridDim.x * blockDim.x;
    if (id < 8) g_bar[id] = 0u;
    for (int i = id; i < 256 * 112; i += stride) {
        int k = i / 112, m = i - k * 112;
        g_W1t[i] = (m < 100) ? W1[m * 256 + k] : 0.f;
    }
    for (int i = id; i < 112 * 112; i += stride) {
        int k = i / 112, m = i - k * 112;
        g_W2t[i] = (k < 100 && m < 100) ? W2[m * 100 + k] : 0.f;
    }
    for (int i = id; i < 112 * 176; i += stride) {
        int k = i / 176, m = i - k * 176;
        g_W3t[i] = (k < 100 && m < 170) ? W3[m * 100 + k] : 0.f;
    }
    for (int i = id; i < 112; i += stride) {
        g_b1p[i] = (i < 100) ? b1[i] : 0.f;
        g_b2p[i] = (i < 100) ? b2[i] : 0.f;
    }
    for (int i = id; i < 176; i += stride) g_b3p[i] = (i < 170) ? b3[i] : 0.f;
}

// ---------------- x-projection ----------------
__global__ void __launch_bounds__(256)
xproj_kernel(const float* __restrict__ x, const float* __restrict__ W_ih)
{
    __shared__ float Ws[IN_DIM][64];
    __shared__ float xs[IN_DIM][64];
    const int tid = threadIdx.x;
    const int t  = blockIdx.x;
    const int jt = blockIdx.y;
    const int bt = blockIdx.z;

    for (int i = tid; i < 64 * IN_DIM; i += 256) {
        int m = i / IN_DIM, c = i - m * IN_DIM;
        Ws[c][m] = W_ih[(jt * 64 + m) * IN_DIM + c];
    }
    for (int i = tid; i < 64 * IN_DIM; i += 256) {
        int n = i / IN_DIM, c = i - n * IN_DIM;
        xs[c][n] = x[((size_t)(bt * 64 + n) * TDIM + t) * IN_DIM + c];
    }
    __syncthreads();

    const int tm = tid >> 4;
    const int tb = tid & 15;
    float acc[4][4];
#pragma unroll
    for (int i = 0; i < 4; ++i)
#pragma unroll
        for (int j = 0; j < 4; ++j) acc[i][j] = 0.f;
#pragma unroll 5
    for (int c = 0; c < IN_DIM; ++c) {
        float4 a  = *reinterpret_cast<const float4*>(&Ws[c][tm << 2]);
        float4 b4 = *reinterpret_cast<const float4*>(&xs[c][tb << 2]);
        float av[4] = {a.x, a.y, a.z, a.w};
        float bv[4] = {b4.x, b4.y, b4.z, b4.w};
#pragma unroll
        for (int i = 0; i < 4; ++i)
#pragma unroll
            for (int j = 0; j < 4; ++j) acc[i][j] = fmaf(av[i], bv[j], acc[i][j]);
    }
    float* dst = g_GX + (size_t)t * 262144 + (size_t)(jt * 64 + (tm << 2)) * 256
                 + bt * 64 + (tb << 2);
#pragma unroll
    for (int i = 0; i < 4; ++i)
        *reinterpret_cast<float4*>(dst + (size_t)i * 256) =
            make_float4(acc[i][0], acc[i][1], acc[i][2], acc[i][3]);
}

__device__ __forceinline__ float sigf(float v)     { return 1.f / (1.f + __expf(-v)); }
__device__ __forceinline__ float tanhfast(float v) { return 1.f - 2.f / (__expf(2.f * v) + 1.f); }
__device__ __forceinline__ float ldcg1(const float* p) {
    float v;
    asm volatile("ld.global.cg.f32 %0,[%1];" : "=f"(v) : "l"(p));
    return v;
}
__device__ __forceinline__ float4 ldcg4(const float* p) {
    float4 v;
    asm volatile("ld.global.cg.v4.f32 {%0,%1,%2,%3},[%4];"
                 : "=f"(v.x), "=f"(v.y), "=f"(v.z), "=f"(v.w) : "l"(p));
    return v;
}
__device__ __forceinline__ uint32_t smem_u32(const void* p) {
    uint32_t a;
    asm("{ .reg .u64 t; cvta.to.shared.u64 t, %1; cvt.u32.u64 %0, t; }" : "=r"(a) : "l"(p));
    return a;
}

// ---------------- mma helpers (sm_80-compatible HMMA path) ----------------
__device__ __forceinline__ void ldsm4(uint32_t* r, uint32_t a) {
    asm volatile("ldmatrix.sync.aligned.m8n8.x4.shared.b16 {%0,%1,%2,%3}, [%4];"
        : "=r"(r[0]), "=r"(r[1]), "=r"(r[2]), "=r"(r[3]) : "r"(a));
}
__device__ __forceinline__ void ldsm2t(uint32_t* r, uint32_t a) {
    asm volatile("ldmatrix.sync.aligned.m8n8.x2.trans.shared.b16 {%0,%1}, [%2];"
        : "=r"(r[0]), "=r"(r[1]) : "r"(a));
}
__device__ __forceinline__ void mma_bf16(float* d, const uint32_t* a, const uint32_t* b) {
    asm volatile("mma.sync.aligned.m16n8k16.row.col.f32.bf16.bf16.f32 "
        "{%0,%1,%2,%3}, {%4,%5,%6,%7}, {%8,%9}, {%0,%1,%2,%3};"
        : "+f"(d[0]), "+f"(d[1]), "+f"(d[2]), "+f"(d[3])
        : "r"(a[0]), "r"(a[1]), "r"(a[2]), "r"(a[3]), "r"(b[0]), "r"(b[1]));
}
__device__ __forceinline__ uint32_t pack_bf(__nv_bfloat16 lo, __nv_bfloat16 hi) {
    return (uint32_t)__bfloat16_as_ushort(lo) | ((uint32_t)__bfloat16_as_ushort(hi) << 16);
}
__device__ __forceinline__ void split2(float v, __nv_bfloat16& a, __nv_bfloat16& b) {
    a = __float2bfloat16(v);
    b = __float2bfloat16(v - __bfloat162float(a));
}

// ---------------- persistent LSTM (HMMA tensor path) ----------------
// grid 148 (>=128 exit): jg = blockIdx>>3 (16 hid-tiles of 16), bg = blockIdx&7 (8 batch-tiles of 32)
// M=64 gate rows (4 gates x 16 jh), N=32, K=256. 512 threads = 16 warps (4 mt x 4 nt tiles).
// 2-split bf16 (hi+residual), 3 significant products into one fp32 accumulator.
#define WSP_OFF  0                    // bf16 [2][m=64][k pad 264]
#define WSP_SPL  33792
#define HSP_OFF  67584                // bf16 [2][k=256][n pad 40]
#define HSP_SPL  20480
#define GS_OFF   108544               // f32 [64][33]
#define BIAS_OFF 116992               // f32 [64]
#define CS_OFF   117248               // f32 [512]
#define LSTM_SMEM_BYTES 119296

__global__ void __launch_bounds__(512, 1)
lstm_kernel(const float* __restrict__ W_hh,
            const float* __restrict__ b_ih, const float* __restrict__ b_hh)
{
    extern __shared__ char smc[];
    if (blockIdx.x >= 128) return;
    const uint32_t sbase = smem_u32(smc);
    float* Gs   = reinterpret_cast<float*>(smc + GS_OFF);
    float* bias = reinterpret_cast<float*>(smc + BIAS_OFF);
    float* cS   = reinterpret_cast<float*>(smc + CS_OFF);

    const int tid = threadIdx.x;
    const int bg  = blockIdx.x & 7;
    const int jg  = blockIdx.x >> 3;

    // one-time W staging: 2 bf16 splits, [m=64][k=256] pad 264
    {
        int m = tid >> 3, kc = tid & 7;
        int j = ((m >> 4) << 8) + (jg << 4) + (m & 15);    // gate*256 + jg*16 + jh
        const float* wrow = W_hh + (size_t)j * 256;
#pragma unroll
        for (int q = 0; q < 4; ++q) {
            int k0 = kc * 32 + q * 8;
            float4 u0 = *reinterpret_cast<const float4*>(wrow + k0);
            float4 u1 = *reinterpret_cast<const float4*>(wrow + k0 + 4);
            __nv_bfloat16 a[8], b[8];
            split2(u0.x, a[0], b[0]); split2(u0.y, a[1], b[1]);
            split2(u0.z, a[2], b[2]); split2(u0.w, a[3], b[3]);
            split2(u1.x, a[4], b[4]); split2(u1.y, a[5], b[5]);
            split2(u1.z, a[6], b[6]); split2(u1.w, a[7], b[7]);
            uint4 qa = make_uint4(pack_bf(a[0], a[1]), pack_bf(a[2], a[3]),
                                  pack_bf(a[4], a[5]), pack_bf(a[6], a[7]));
            uint4 qb = make_uint4(pack_bf(b[0], b[1]), pack_bf(b[2], b[3]),
                                  pack_bf(b[4], b[5]), pack_bf(b[6], b[7]));
            *reinterpret_cast<uint4*>(smc + WSP_OFF + m * 528 + k0 * 2) = qa;
            *reinterpret_cast<uint4*>(smc + WSP_OFF + WSP_SPL + m * 528 + k0 * 2) = qb;
        }
    }
    if (tid < 64) {
        int j = ((tid >> 4) << 8) + (jg << 4) + (tid & 15);
        bias[tid] = b_ih[j] + b_hh[j];
    }
    if (tid < 512) cS[tid] = 0.f;
    for (int i = tid; i < 64 * 33; i += 512) Gs[i] = 0.f;
    __syncthreads();

    // GEMM role: warp = (mt, nt); lane owns fragment slots
    const int wid  = tid >> 5;
    const int lane = tid & 31;
    const int mt = wid >> 2, nt = wid & 3;
    const uint32_t aA0 = sbase + WSP_OFF +
        (uint32_t)(mt * 16 + (lane & 15)) * 528 + ((lane >> 4) * 16);
    const uint32_t aA1 = aA0 + WSP_SPL;
    const uint32_t aB0 = sbase + HSP_OFF + (uint32_t)(lane & 15) * 80 + nt * 16;
    const uint32_t aB1 = aB0 + HSP_SPL;

    // combine role
    const int cjh = tid >> 5;          // 0..15
    const int cn  = tid & 31;
    const size_t gxoff = (size_t)((jg << 4) + cjh) * 256 + (bg << 5) + cn;
    const int jh_g = (jg << 4) + cjh;

    // staging role
    const int sn4 = (tid & 7) << 2;    // n quad
    const int skb = tid >> 3;          // k 0..63 (+64i)

    for (int t = 0; t < NSTEP; ++t) {
        // early gx loads
        const float* gp = g_GX + (size_t)t * 262144 + gxoff;
        float gxi = ldcg1(gp);
        float gxf = ldcg1(gp + 65536);
        float gxg = ldcg1(gp + 131072);
        float gxo = ldcg1(gp + 196608);

        // stage h(t-1): [k][b] fp32 -> 2 bf16 splits [k][n pad 40] (no transpose)
        if (t > 0) {
            const float* hp = g_H + (size_t)(t - 1) * 65536 + (bg << 5) + sn4;
#pragma unroll
            for (int i = 0; i < 4; ++i) {
                int k = skb + (i << 6);
                float4 v = ldcg4(hp + (size_t)k * 256);
                __nv_bfloat16 a0, b0, a1, b1, a2, b2, a3, b3;
                split2(v.x, a0, b0); split2(v.y, a1, b1);
                split2(v.z, a2, b2); split2(v.w, a3, b3);
                *reinterpret_cast<uint2*>(smc + HSP_OFF + k * 80 + sn4 * 2) =
                    make_uint2(pack_bf(a0, a1), pack_bf(a2, a3));
                *reinterpret_cast<uint2*>(smc + HSP_OFF + HSP_SPL + k * 80 + sn4 * 2) =
                    make_uint2(pack_bf(b0, b1), pack_bf(b2, b3));
            }
        }
        __syncthreads();

        // tensor GEMM: 3 products (hi*hi, hi*res, res*hi) into one fp32 D tile
        if (t > 0) {
            float d[4] = {0.f, 0.f, 0.f, 0.f};
#pragma unroll
            for (int kk = 0; kk < 16; ++kk) {
                uint32_t a0[4], a1[4], b0[2], b1[2];
                ldsm4(a0, aA0 + kk * 32);
                ldsm4(a1, aA1 + kk * 32);
                ldsm2t(b0, aB0 + kk * 1280);
                ldsm2t(b1, aB1 + kk * 1280);
                mma_bf16(d, a0, b0);
                mma_bf16(d, a0, b1);
                mma_bf16(d, a1, b0);
            }
            int r = lane >> 2, c2 = (lane & 3) << 1;
            float* g0 = Gs + (mt * 16 + r) * 33 + (nt << 3) + c2;
            g0[0] = d[0]; g0[1] = d[1];
            g0[8 * 33] = d[2]; g0[8 * 33 + 1] = d[3];
        }
        __syncthreads();

        // combine: 1 cell/thread (jh=cjh, n=cn); gates at rows gate*16+jh
        {
            float vi = gxi + bias[cjh]      + Gs[(cjh)      * 33 + cn];
            float vf = gxf + bias[16 + cjh] + Gs[(16 + cjh) * 33 + cn];
            float vg = gxg + bias[32 + cjh] + Gs[(32 + cjh) * 33 + cn];
            float vo = gxo + bias[48 + cjh] + Gs[(48 + cjh) * 33 + cn];
            float iv = sigf(vi), fv = sigf(vf), gv = tanhfast(vg), ov = sigf(vo);
            float cv = fv * cS[tid] + iv * gv;
            cS[tid] = cv;
            g_H[(size_t)t * 65536 + (size_t)jh_g * 256 + (bg << 5) + cn] = ov * tanhfast(cv);
        }
        __syncthreads();

        // inter-block barrier (16 jg-blocks sharing this bg)
        if (tid == 0) {
            __threadfence();
            asm volatile("red.release.gpu.global.add.u32 [%0],%1;"
                         :: "l"(&g_bar[bg]), "r"(1u) : "memory");
            unsigned target = (unsigned)(t + 1) << 4;
            unsigned v;
            for (;;) {
                asm volatile("ld.acquire.gpu.global.u32 %0,[%1];"
                             : "=r"(v) : "l"(&g_bar[bg]));
                if (v >= target) break;
                __nanosleep(32);
            }
        }
        __syncthreads();
    }
}

// ---------------- MDN head ----------------
__device__ __forceinline__ void mdn_gemm(
    const float* __restrict__ At, int ldA, int mTiles, int K,
    const float* __restrict__ Bs, int ldb, float* __restrict__ Cs,
    const float* __restrict__ biasv, bool relu)
{
    for (int tile = threadIdx.x; tile < mTiles * 8; tile += blockDim.x) {
        int tm = tile % mTiles, tb = tile / mTiles;
        int m = tm << 2;
        const float* Ap = At + m;
        const float* Bp = Bs + (tb << 2);
        float acc[4][4];
#pragma unroll
        for (int i = 0; i < 4; ++i)
#pragma unroll
            for (int j = 0; j < 4; ++j) acc[i][j] = 0.f;
#pragma unroll 4
        for (int k = 0; k < K; ++k) {
            float4 a  = *reinterpret_cast<const float4*>(Ap + k * ldA);
            float4 b4 = *reinterpret_cast<const float4*>(Bp + k * ldb);
            float av[4] = {a.x, a.y, a.z, a.w};
            float bv[4] = {b4.x, b4.y, b4.z, b4.w};
#pragma unroll
            for (int i = 0; i < 4; ++i)
#pragma unroll
                for (int j = 0; j < 4; ++j) acc[i][j] = fmaf(av[i], bv[j], acc[i][j]);
        }
#pragma unroll
        for (int i = 0; i < 4; ++i) {
            float bv = biasv[m + i];
            float4 r = make_float4(acc[i][0] + bv, acc[i][1] + bv,
                                   acc[i][2] + bv, acc[i][3] + bv);
            if (relu) { r.x = fmaxf(r.x, 0.f); r.y = fmaxf(r.y, 0.f);
                        r.z = fmaxf(r.z, 0.f); r.w = fmaxf(r.w, 0.f); }
            *reinterpret_cast<float4*>(&Cs[(m + i) * 36 + (tb << 2)]) = r;
        }
    }
}

#define MDN_SMEM_BYTES ((256*32 + 112*36 + 176*36) * 4)

__global__ void __launch_bounds__(256, 2)
mdn_kernel(float* __restrict__ out)
{
    extern __shared__ float sm[];
    float* hT = sm;                 // [256][32], reused as h2 [112][36]
    float* h1 = hT + 256 * 32;      // [112][36]
    float* o3 = h1 + 112 * 36;      // [176][36]

    const int tid = threadIdx.x;
    const int t   = blockIdx.x >> 3;
    const int bg  = blockIdx.x & 7;

    const float* hp = g_H + (size_t)t * 65536 + (bg << 5);
    for (int i = tid; i < 2048; i += 256) {
        int k = i >> 3, nb = i & 7;
        float4 v = *reinterpret_cast<const float4*>(hp + (size_t)k * 256 + (nb << 2));
        *reinterpret_cast<float4*>(&hT[k * 32 + (nb << 2)]) = v;
    }
    __syncthreads();

    mdn_gemm(g_W1t, 112, 28, 256, hT, 32, h1, g_b1p, true);
    __syncthreads();
    mdn_gemm(g_W2t, 112, 28, 112, h1, 36, hT, g_b2p, true);   // h2 -> hT (reuse)
    __syncthreads();
    mdn_gemm(g_W3t, 176, 44, 112, hT, 36, o3, g_b3p, false);
    __syncthreads();

    if (tid < 32) {
        int n = tid;
        size_t r = (size_t)((bg << 5) + n) * NSTEP + t;
        float l[5];
        float mx = -1e30f;
#pragma unroll
        for (int k = 0; k < 5; ++k) { l[k] = o3[k * 36 + n]; mx = fmaxf(mx, l[k]); }
        float s = 0.f;
#pragma unroll
        for (int k = 0; k < 5; ++k) { l[k] = __expf(l[k] - mx); s += l[k]; }
        float inv = 1.f / s;
#pragma unroll
        for (int k = 0; k < 5; ++k) out[r * 5 + k] = l[k] * inv;
#pragma unroll
        for (int k = 0; k < 5; ++k)
            out[VARBASE + r * 5 + k] = __expf(o3[(5 + k) * 36 + n]);
    }
    for (int i = tid; i < 5120; i += 256) {
        int n = i / 160, j = i - n * 160;
        size_t r = (size_t)((bg << 5) + n) * NSTEP + t;
        out[MEANBASE + r * 160 + j] = o3[(10 + j) * 36 + n];
    }
}

extern "C" void kernel_launch(void* const* d_in, const int* in_sizes, int n_in,
                              void* d_out, int out_size)
{
    const float* x    = (const float*)d_in[0];
    const float* W_ih = (const float*)d_in[1];
    const float* W_hh = (const float*)d_in[2];
    const float* b_ih = (const float*)d_in[3];
    const float* b_hh = (const float*)d_in[4];
    const float* W1   = (const float*)d_in[5];
    const float* b1   = (const float*)d_in[6];
    const float* W2   = (const float*)d_in[7];
    const float* b2   = (const float*)d_in[8];
    const float* W3   = (const float*)d_in[9];
    const float* b3   = (const float*)d_in[10];
    float* out = (float*)d_out;

    cudaFuncSetAttribute(lstm_kernel, cudaFuncAttributeMaxDynamicSharedMemorySize, LSTM_SMEM_BYTES);
    cudaFuncSetAttribute(mdn_kernel,  cudaFuncAttributeMaxDynamicSharedMemorySize, MDN_SMEM_BYTES);

    prep_w<<<128, 256>>>(W1, b1, W2, b2, W3, b3);
    xproj_kernel<<<dim3(NSTEP, 16, 4), 256>>>(x, W_ih);
    lstm_kernel<<<148, 512, LSTM_SMEM_BYTES>>>(W_hh, b_ih, b_hh);
    mdn_kernel<<<NSTEP * 8, 256, MDN_SMEM_BYTES>>>(out);
}

// round 13
// speedup vs baseline: 2.2380x; 1.0814x over previous
#include <cuda_runtime.h>
#include <cuda_bf16.h>
#include <cstdint>

#define TDIM   1024
#define NSTEP  1023
#define IN_DIM 35

// output layout: coeff [256][1023][5] | mean [256][1023][5][32] | var [256][1023][5]
#define MEANBASE 1309440
#define VARBASE  43211520

// ---------------- device scratch (allocation-free) ----------------
__device__ float g_H[(size_t)NSTEP * 256 * 256];    // h history, [t][k=256][b=256]
__device__ float g_GX[(size_t)NSTEP * 1024 * 256];  // x-projection, [t][j=1024][b=256]
__device__ float g_W1t[256 * 112];
__device__ float g_W2t[112 * 112];
__device__ float g_W3t[112 * 176];
__device__ float g_b1p[112];
__device__ float g_b2p[112];
__device__ float g_b3p[176];
__device__ unsigned g_bar[8];

// ---------------- prep ----------------
__global__ void prep_w(const float* __restrict__ W1, const float* __restrict__ b1,
                       const float* __restrict__ W2, const float* __restrict__ b2,
                       const float* __restrict__ W3, const float* __restrict__ b3)
{
    int id = blockIdx.x * blockDim.x + threadIdx.x;
    int stride = gridDim.x * blockDim.x;
    if (id < 8) g_bar[id] = 0u;
    for (int i = id; i < 256 * 112; i += stride) {
        int k = i / 112, m = i - k * 112;
        g_W1t[i] = (m < 100) ? W1[m * 256 + k] : 0.f;
    }
    for (int i = id; i < 112 * 112; i += stride) {
        int k = i / 112, m = i - k * 112;
        g_W2t[i] = (k < 100 && m < 100) ? W2[m * 100 + k] : 0.f;
    }
    for (int i = id; i < 112 * 176; i += stride) {
        int k = i / 176, m = i - k * 176;
        g_W3t[i] = (k < 100 && m < 170) ? W3[m * 100 + k] : 0.f;
    }
    for (int i = id; i < 112; i += stride) {
        g_b1p[i] = (i < 100) ? b1[i] : 0.f;
        g_b2p[i] = (i < 100) ? b2[i] : 0.f;
    }
    for (int i = id; i < 176; i += stride) g_b3p[i] = (i < 170) ? b3[i] : 0.f;
}

// ---------------- x-projection ----------------
__global__ void __launch_bounds__(256)
xproj_kernel(const float* __restrict__ x, const float* __restrict__ W_ih)
{
    __shared__ float Ws[IN_DIM][64];
    __shared__ float xs[IN_DIM][64];
    const int tid = threadIdx.x;
    const int t  = blockIdx.x;
    const int jt = blockIdx.y;
    const int bt = blockIdx.z;

    for (int i = tid; i < 64 * IN_DIM; i += 256) {
        int m = i / IN_DIM, c = i - m * IN_DIM;
        Ws[c][m] = W_ih[(jt * 64 + m) * IN_DIM + c];
    }
    for (int i = tid; i < 64 * IN_DIM; i += 256) {
        int n = i / IN_DIM, c = i - n * IN_DIM;
        xs[c][n] = x[((size_t)(bt * 64 + n) * TDIM + t) * IN_DIM + c];
    }
    __syncthreads();

    const int tm = tid >> 4;
    const int tb = tid & 15;
    float acc[4][4];
#pragma unroll
    for (int i = 0; i < 4; ++i)
#pragma unroll
        for (int j = 0; j < 4; ++j) acc[i][j] = 0.f;
#pragma unroll 5
    for (int c = 0; c < IN_DIM; ++c) {
        float4 a  = *reinterpret_cast<const float4*>(&Ws[c][tm << 2]);
        float4 b4 = *reinterpret_cast<const float4*>(&xs[c][tb << 2]);
        float av[4] = {a.x, a.y, a.z, a.w};
        float bv[4] = {b4.x, b4.y, b4.z, b4.w};
#pragma unroll
        for (int i = 0; i < 4; ++i)
#pragma unroll
            for (int j = 0; j < 4; ++j) acc[i][j] = fmaf(av[i], bv[j], acc[i][j]);
    }
    float* dst = g_GX + (size_t)t * 262144 + (size_t)(jt * 64 + (tm << 2)) * 256
                 + bt * 64 + (tb << 2);
#pragma unroll
    for (int i = 0; i < 4; ++i)
        *reinterpret_cast<float4*>(dst + (size_t)i * 256) =
            make_float4(acc[i][0], acc[i][1], acc[i][2], acc[i][3]);
}

__device__ __forceinline__ float sigf(float v)     { return 1.f / (1.f + __expf(-v)); }
__device__ __forceinline__ float tanhfast(float v) { return 1.f - 2.f / (__expf(2.f * v) + 1.f); }
__device__ __forceinline__ float ldcg1(const float* p) {
    float v;
    asm volatile("ld.global.cg.f32 %0,[%1];" : "=f"(v) : "l"(p));
    return v;
}
__device__ __forceinline__ float4 ldcg4(const float* p) {
    float4 v;
    asm volatile("ld.global.cg.v4.f32 {%0,%1,%2,%3},[%4];"
                 : "=f"(v.x), "=f"(v.y), "=f"(v.z), "=f"(v.w) : "l"(p));
    return v;
}
__device__ __forceinline__ uint32_t smem_u32(const void* p) {
    uint32_t a;
    asm("{ .reg .u64 t; cvta.to.shared.u64 t, %1; cvt.u32.u64 %0, t; }" : "=r"(a) : "l"(p));
    return a;
}

// ---------------- mma helpers (sm_80-compatible HMMA path) ----------------
__device__ __forceinline__ void ldsm4(uint32_t* r, uint32_t a) {
    asm volatile("ldmatrix.sync.aligned.m8n8.x4.shared.b16 {%0,%1,%2,%3}, [%4];"
        : "=r"(r[0]), "=r"(r[1]), "=r"(r[2]), "=r"(r[3]) : "r"(a));
}
__device__ __forceinline__ void ldsm2t(uint32_t* r, uint32_t a) {
    asm volatile("ldmatrix.sync.aligned.m8n8.x2.trans.shared.b16 {%0,%1}, [%2];"
        : "=r"(r[0]), "=r"(r[1]) : "r"(a));
}
__device__ __forceinline__ void mma_bf16(float* d, const uint32_t* a, const uint32_t* b) {
    asm volatile("mma.sync.aligned.m16n8k16.row.col.f32.bf16.bf16.f32 "
        "{%0,%1,%2,%3}, {%4,%5,%6,%7}, {%8,%9}, {%0,%1,%2,%3};"
        : "+f"(d[0]), "+f"(d[1]), "+f"(d[2]), "+f"(d[3])
        : "r"(a[0]), "r"(a[1]), "r"(a[2]), "r"(a[3]), "r"(b[0]), "r"(b[1]));
}
__device__ __forceinline__ uint32_t pack_bf(__nv_bfloat16 lo, __nv_bfloat16 hi) {
    return (uint32_t)__bfloat16_as_ushort(lo) | ((uint32_t)__bfloat16_as_ushort(hi) << 16);
}
__device__ __forceinline__ void split2(float v, __nv_bfloat16& a, __nv_bfloat16& b) {
    a = __float2bfloat16(v);
    b = __float2bfloat16(v - __bfloat162float(a));
}

// ---------------- persistent LSTM (HMMA tensor path) ----------------
// grid 148 (>=128 exit): jg = blockIdx>>3 (16 hid-tiles of 16), bg = blockIdx&7 (8 batch-tiles of 32)
// M=64 gate rows, N=32, K=256. 512 threads = 16 warps (4 mt x 4 nt).
// W 2-split bf16 (exact), h single bf16: gates = fp32(W) x bf16(h). 2 MMA products.
#define WSP_OFF  0                    // bf16 [2][m=64][k pad 264]
#define WSP_SPL  33792
#define HSP_OFF  67584                // bf16 [k=256][n pad 40]
#define GS_OFF   88064                // f32 [64][33]
#define BIAS_OFF 96512                // f32 [64]
#define CS_OFF   96768                // f32 [512]
#define LSTM_SMEM_BYTES 98816

__global__ void __launch_bounds__(512, 1)
lstm_kernel(const float* __restrict__ W_hh,
            const float* __restrict__ b_ih, const float* __restrict__ b_hh)
{
    extern __shared__ char smc[];
    if (blockIdx.x >= 128) return;
    const uint32_t sbase = smem_u32(smc);
    float* Gs   = reinterpret_cast<float*>(smc + GS_OFF);
    float* bias = reinterpret_cast<float*>(smc + BIAS_OFF);
    float* cS   = reinterpret_cast<float*>(smc + CS_OFF);

    const int tid = threadIdx.x;
    const int bg  = blockIdx.x & 7;
    const int jg  = blockIdx.x >> 3;

    // one-time W staging: 2 bf16 splits (exact decomposition), [m=64][k=256] pad 264
    {
        int m = tid >> 3, kc = tid & 7;
        int j = ((m >> 4) << 8) + (jg << 4) + (m & 15);    // gate*256 + jg*16 + jh
        const float* wrow = W_hh + (size_t)j * 256;
#pragma unroll
        for (int q = 0; q < 4; ++q) {
            int k0 = kc * 32 + q * 8;
            float4 u0 = *reinterpret_cast<const float4*>(wrow + k0);
            float4 u1 = *reinterpret_cast<const float4*>(wrow + k0 + 4);
            __nv_bfloat16 a[8], b[8];
            split2(u0.x, a[0], b[0]); split2(u0.y, a[1], b[1]);
            split2(u0.z, a[2], b[2]); split2(u0.w, a[3], b[3]);
            split2(u1.x, a[4], b[4]); split2(u1.y, a[5], b[5]);
            split2(u1.z, a[6], b[6]); split2(u1.w, a[7], b[7]);
            uint4 qa = make_uint4(pack_bf(a[0], a[1]), pack_bf(a[2], a[3]),
                                  pack_bf(a[4], a[5]), pack_bf(a[6], a[7]));
            uint4 qb = make_uint4(pack_bf(b[0], b[1]), pack_bf(b[2], b[3]),
                                  pack_bf(b[4], b[5]), pack_bf(b[6], b[7]));
            *reinterpret_cast<uint4*>(smc + WSP_OFF + m * 528 + k0 * 2) = qa;
            *reinterpret_cast<uint4*>(smc + WSP_OFF + WSP_SPL + m * 528 + k0 * 2) = qb;
        }
    }
    if (tid < 64) {
        int j = ((tid >> 4) << 8) + (jg << 4) + (tid & 15);
        bias[tid] = b_ih[j] + b_hh[j];
    }
    if (tid < 512) cS[tid] = 0.f;
    for (int i = tid; i < 64 * 33; i += 512) Gs[i] = 0.f;
    __syncthreads();

    // GEMM role
    const int wid  = tid >> 5;
    const int lane = tid & 31;
    const int mt = wid >> 2, nt = wid & 3;
    const uint32_t aA0 = sbase + WSP_OFF +
        (uint32_t)(mt * 16 + (lane & 15)) * 528 + ((lane >> 4) * 16);
    const uint32_t aA1 = aA0 + WSP_SPL;
    const uint32_t aB0 = sbase + HSP_OFF + (uint32_t)(lane & 15) * 80 + nt * 16;

    // combine role
    const int cjh = tid >> 5;
    const int cn  = tid & 31;
    const size_t gxoff = (size_t)((jg << 4) + cjh) * 256 + (bg << 5) + cn;
    const int jh_g = (jg << 4) + cjh;

    // staging role
    const int sn4 = (tid & 7) << 2;
    const int skb = tid >> 3;

    for (int t = 0; t < NSTEP; ++t) {
        // early gx loads
        const float* gp = g_GX + (size_t)t * 262144 + gxoff;
        float gxi = ldcg1(gp);
        float gxf = ldcg1(gp + 65536);
        float gxg = ldcg1(gp + 131072);
        float gxo = ldcg1(gp + 196608);

        // stage h(t-1): [k][b] fp32 -> single bf16 [k][n pad 40]
        if (t > 0) {
            const float* hp = g_H + (size_t)(t - 1) * 65536 + (bg << 5) + sn4;
#pragma unroll
            for (int i = 0; i < 4; ++i) {
                int k = skb + (i << 6);
                float4 v = ldcg4(hp + (size_t)k * 256);
                uint32_t p0 = pack_bf(__float2bfloat16(v.x), __float2bfloat16(v.y));
                uint32_t p1 = pack_bf(__float2bfloat16(v.z), __float2bfloat16(v.w));
                *reinterpret_cast<uint2*>(smc + HSP_OFF + k * 80 + sn4 * 2) =
                    make_uint2(p0, p1);
            }
        }
        __syncthreads();

        // tensor GEMM: 2 products (W_hi*h, W_res*h) into one fp32 D tile
        if (t > 0) {
            float d[4] = {0.f, 0.f, 0.f, 0.f};
#pragma unroll
            for (int kk = 0; kk < 16; ++kk) {
                uint32_t a0[4], a1[4], b0[2];
                ldsm4(a0, aA0 + kk * 32);
                ldsm4(a1, aA1 + kk * 32);
                ldsm2t(b0, aB0 + kk * 1280);
                mma_bf16(d, a0, b0);
                mma_bf16(d, a1, b0);
            }
            int r = lane >> 2, c2 = (lane & 3) << 1;
            float* g0 = Gs + (mt * 16 + r) * 33 + (nt << 3) + c2;
            g0[0] = d[0]; g0[1] = d[1];
            g0[8 * 33] = d[2]; g0[8 * 33 + 1] = d[3];
        }
        __syncthreads();

        // combine: 1 cell/thread (jh=cjh, n=cn)
        {
            float vi = gxi + bias[cjh]      + Gs[(cjh)      * 33 + cn];
            float vf = gxf + bias[16 + cjh] + Gs[(16 + cjh) * 33 + cn];
            float vg = gxg + bias[32 + cjh] + Gs[(32 + cjh) * 33 + cn];
            float vo = gxo + bias[48 + cjh] + Gs[(48 + cjh) * 33 + cn];
            float iv = sigf(vi), fv = sigf(vf), gv = tanhfast(vg), ov = sigf(vo);
            float cv = fv * cS[tid] + iv * gv;
            cS[tid] = cv;
            g_H[(size_t)t * 65536 + (size_t)jh_g * 256 + (bg << 5) + cn] = ov * tanhfast(cv);
        }
        __syncthreads();

        // inter-block barrier (16 jg-blocks sharing this bg)
        if (tid == 0) {
            __threadfence();
            asm volatile("red.release.gpu.global.add.u32 [%0],%1;"
                         :: "l"(&g_bar[bg]), "r"(1u) : "memory");
            unsigned target = (unsigned)(t + 1) << 4;
            unsigned v;
            for (;;) {
                asm volatile("ld.acquire.gpu.global.u32 %0,[%1];"
                             : "=r"(v) : "l"(&g_bar[bg]));
                if (v >= target) break;
                __nanosleep(32);
            }
        }
        __syncthreads();
    }
}

// ---------------- MDN head ----------------
__device__ __forceinline__ void mdn_gemm(
    const float* __restrict__ At, int ldA, int mTiles, int K,
    const float* __restrict__ Bs, int ldb, float* __restrict__ Cs,
    const float* __restrict__ biasv, bool relu)
{
    for (int tile = threadIdx.x; tile < mTiles * 8; tile += blockDim.x) {
        int tm = tile % mTiles, tb = tile / mTiles;
        int m = tm << 2;
        const float* Ap = At + m;
        const float* Bp = Bs + (tb << 2);
        float acc[4][4];
#pragma unroll
        for (int i = 0; i < 4; ++i)
#pragma unroll
            for (int j = 0; j < 4; ++j) acc[i][j] = 0.f;
#pragma unroll 4
        for (int k = 0; k < K; ++k) {
            float4 a  = *reinterpret_cast<const float4*>(Ap + k * ldA);
            float4 b4 = *reinterpret_cast<const float4*>(Bp + k * ldb);
            float av[4] = {a.x, a.y, a.z, a.w};
            float bv[4] = {b4.x, b4.y, b4.z, b4.w};
#pragma unroll
            for (int i = 0; i < 4; ++i)
#pragma unroll
                for (int j = 0; j < 4; ++j) acc[i][j] = fmaf(av[i], bv[j], acc[i][j]);
        }
#pragma unroll
        for (int i = 0; i < 4; ++i) {
            float bv = biasv[m + i];
            float4 r = make_float4(acc[i][0] + bv, acc[i][1] + bv,
                                   acc[i][2] + bv, acc[i][3] + bv);
            if (relu) { r.x = fmaxf(r.x, 0.f); r.y = fmaxf(r.y, 0.f);
                        r.z = fmaxf(r.z, 0.f); r.w = fmaxf(r.w, 0.f); }
            *reinterpret_cast<float4*>(&Cs[(m + i) * 36 + (tb << 2)]) = r;
        }
    }
}

#define MDN_SMEM_BYTES ((256*32 + 112*36 + 176*36) * 4)

__global__ void __launch_bounds__(256, 2)
mdn_kernel(float* __restrict__ out)
{
    extern __shared__ float sm[];
    float* hT = sm;                 // [256][32], reused as h2 [112][36]
    float* h1 = hT + 256 * 32;      // [112][36]
    float* o3 = h1 + 112 * 36;      // [176][36]

    const int tid = threadIdx.x;
    const int t   = blockIdx.x >> 3;
    const int bg  = blockIdx.x & 7;

    const float* hp = g_H + (size_t)t * 65536 + (bg << 5);
    for (int i = tid; i < 2048; i += 256) {
        int k = i >> 3, nb = i & 7;
        float4 v = *reinterpret_cast<const float4*>(hp + (size_t)k * 256 + (nb << 2));
        *reinterpret_cast<float4*>(&hT[k * 32 + (nb << 2)]) = v;
    }
    __syncthreads();

    mdn_gemm(g_W1t, 112, 28, 256, hT, 32, h1, g_b1p, true);
    __syncthreads();
    mdn_gemm(g_W2t, 112, 28, 112, h1, 36, hT, g_b2p, true);   // h2 -> hT (reuse)
    __syncthreads();
    mdn_gemm(g_W3t, 176, 44, 112, hT, 36, o3, g_b3p, false);
    __syncthreads();

    if (tid < 32) {
        int n = tid;
        size_t r = (size_t)((bg << 5) + n) * NSTEP + t;
        float l[5];
        float mx = -1e30f;
#pragma unroll
        for (int k = 0; k < 5; ++k) { l[k] = o3[k * 36 + n]; mx = fmaxf(mx, l[k]); }
        float s = 0.f;
#pragma unroll
        for (int k = 0; k < 5; ++k) { l[k] = __expf(l[k] - mx); s += l[k]; }
        float inv = 1.f / s;
#pragma unroll
        for (int k = 0; k < 5; ++k) out[r * 5 + k] = l[k] * inv;
#pragma unroll
        for (int k = 0; k < 5; ++k)
            out[VARBASE + r * 5 + k] = __expf(o3[(5 + k) * 36 + n]);
    }
    for (int i = tid; i < 5120; i += 256) {
        int n = i / 160, j = i - n * 160;
        size_t r = (size_t)((bg << 5) + n) * NSTEP + t;
        out[MEANBASE + r * 160 + j] = o3[(10 + j) * 36 + n];
    }
}

extern "C" void kernel_launch(void* const* d_in, const int* in_sizes, int n_in,
                              void* d_out, int out_size)
{
    const float* x    = (const float*)d_in[0];
    const float* W_ih = (const float*)d_in[1];
    const float* W_hh = (const float*)d_in[2];
    const float* b_ih = (const float*)d_in[3];
    const float* b_hh = (const float*)d_in[4];
    const float* W1   = (const float*)d_in[5];
    const float* b1   = (const float*)d_in[6];
    const float* W2   = (const float*)d_in[7];
    const float* b2   = (const float*)d_in[8];
    const float* W3   = (const float*)d_in[9];
    const float* b3   = (const float*)d_in[10];
    float* out = (float*)d_out;

    cudaFuncSetAttribute(lstm_kernel, cudaFuncAttributeMaxDynamicSharedMemorySize, LSTM_SMEM_BYTES);
    cudaFuncSetAttribute(mdn_kernel,  cudaFuncAttributeMaxDynamicSharedMemorySize, MDN_SMEM_BYTES);

    prep_w<<<128, 256>>>(W1, b1, W2, b2, W3, b3);
    xproj_kernel<<<dim3(NSTEP, 16, 4), 256>>>(x, W_ih);
    lstm_kernel<<<148, 512, LSTM_SMEM_BYTES>>>(W_hh, b_ih, b_hh);
    mdn_kernel<<<NSTEP * 8, 256, MDN_SMEM_BYTES>>>(out);
}

// round 14
// speedup vs baseline: 2.2643x; 1.0118x over previous
#include <cuda_runtime.h>
#include <cuda_bf16.h>
#include <cstdint>

#define TDIM   1024
#define NSTEP  1023
#define IN_DIM 35

// output layout: coeff [256][1023][5] | mean [256][1023][5][32] | var [256][1023][5]
#define MEANBASE 1309440
#define VARBASE  43211520

// ---------------- device scratch (allocation-free) ----------------
__device__ float g_H[(size_t)NSTEP * 256 * 256];            // fp32 h, [t][k][b] (MDN)
__device__ __nv_bfloat16 g_Hb[(size_t)NSTEP * 256 * 256];   // bf16 h (recurrence)
__device__ float g_GX[(size_t)NSTEP * 1024 * 256];          // x-projection [t][j][b]
__device__ float g_W1t[256 * 112];
__device__ float g_W2t[112 * 112];
__device__ float g_W3t[112 * 176];
__device__ float g_b1p[112];
__device__ float g_b2p[112];
__device__ float g_b3p[176];
__device__ unsigned g_bar[8];

// ---------------- prep ----------------
__global__ void prep_w(const float* __restrict__ W1, const float* __restrict__ b1,
                       const float* __restrict__ W2, const float* __restrict__ b2,
                       const float* __restrict__ W3, const float* __restrict__ b3)
{
    int id = blockIdx.x * blockDim.x + threadIdx.x;
    int stride = gridDim.x * blockDim.x;
    if (id < 8) g_bar[id] = 0u;
    for (int i = id; i < 256 * 112; i += stride) {
        int k = i / 112, m = i - k * 112;
        g_W1t[i] = (m < 100) ? W1[m * 256 + k] : 0.f;
    }
    for (int i = id; i < 112 * 112; i += stride) {
        int k = i / 112, m = i - k * 112;
        g_W2t[i] = (k < 100 && m < 100) ? W2[m * 100 + k] : 0.f;
    }
    for (int i = id; i < 112 * 176; i += stride) {
        int k = i / 176, m = i - k * 176;
        g_W3t[i] = (k < 100 && m < 170) ? W3[m * 100 + k] : 0.f;
    }
    for (int i = id; i < 112; i += stride) {
        g_b1p[i] = (i < 100) ? b1[i] : 0.f;
        g_b2p[i] = (i < 100) ? b2[i] : 0.f;
    }
    for (int i = id; i < 176; i += stride) g_b3p[i] = (i < 170) ? b3[i] : 0.f;
}

// ---------------- x-projection ----------------
__global__ void __launch_bounds__(256)
xproj_kernel(const float* __restrict__ x, const float* __restrict__ W_ih)
{
    __shared__ float Ws[IN_DIM][64];
    __shared__ float xs[IN_DIM][64];
    const int tid = threadIdx.x;
    const int t  = blockIdx.x;
    const int jt = blockIdx.y;
    const int bt = blockIdx.z;

    for (int i = tid; i < 64 * IN_DIM; i += 256) {
        int m = i / IN_DIM, c = i - m * IN_DIM;
        Ws[c][m] = W_ih[(jt * 64 + m) * IN_DIM + c];
    }
    for (int i = tid; i < 64 * IN_DIM; i += 256) {
        int n = i / IN_DIM, c = i - n * IN_DIM;
        xs[c][n] = x[((size_t)(bt * 64 + n) * TDIM + t) * IN_DIM + c];
    }
    __syncthreads();

    const int tm = tid >> 4;
    const int tb = tid & 15;
    float acc[4][4];
#pragma unroll
    for (int i = 0; i < 4; ++i)
#pragma unroll
        for (int j = 0; j < 4; ++j) acc[i][j] = 0.f;
#pragma unroll 5
    for (int c = 0; c < IN_DIM; ++c) {
        float4 a  = *reinterpret_cast<const float4*>(&Ws[c][tm << 2]);
        float4 b4 = *reinterpret_cast<const float4*>(&xs[c][tb << 2]);
        float av[4] = {a.x, a.y, a.z, a.w};
        float bv[4] = {b4.x, b4.y, b4.z, b4.w};
#pragma unroll
        for (int i = 0; i < 4; ++i)
#pragma unroll
            for (int j = 0; j < 4; ++j) acc[i][j] = fmaf(av[i], bv[j], acc[i][j]);
    }
    float* dst = g_GX + (size_t)t * 262144 + (size_t)(jt * 64 + (tm << 2)) * 256
                 + bt * 64 + (tb << 2);
#pragma unroll
    for (int i = 0; i < 4; ++i)
        *reinterpret_cast<float4*>(dst + (size_t)i * 256) =
            make_float4(acc[i][0], acc[i][1], acc[i][2], acc[i][3]);
}

__device__ __forceinline__ float sigf(float v)     { return 1.f / (1.f + __expf(-v)); }
__device__ __forceinline__ float tanhfast(float v) { return 1.f - 2.f / (__expf(2.f * v) + 1.f); }
__device__ __forceinline__ float ldcg1(const float* p) {
    float v;
    asm volatile("ld.global.cg.f32 %0,[%1];" : "=f"(v) : "l"(p));
    return v;
}
__device__ __forceinline__ uint2 ldcg2u(const void* p) {
    uint2 v;
    asm volatile("ld.global.cg.v2.u32 {%0,%1},[%2];" : "=r"(v.x), "=r"(v.y) : "l"(p));
    return v;
}
__device__ __forceinline__ uint32_t smem_u32(const void* p) {
    uint32_t a;
    asm("{ .reg .u64 t; cvta.to.shared.u64 t, %1; cvt.u32.u64 %0, t; }" : "=r"(a) : "l"(p));
    return a;
}

// ---------------- mma helpers ----------------
__device__ __forceinline__ void ldsm4(uint32_t* r, uint32_t a) {
    asm volatile("ldmatrix.sync.aligned.m8n8.x4.shared.b16 {%0,%1,%2,%3}, [%4];"
        : "=r"(r[0]), "=r"(r[1]), "=r"(r[2]), "=r"(r[3]) : "r"(a));
}
__device__ __forceinline__ void ldsm2t(uint32_t* r, uint32_t a) {
    asm volatile("ldmatrix.sync.aligned.m8n8.x2.trans.shared.b16 {%0,%1}, [%2];"
        : "=r"(r[0]), "=r"(r[1]) : "r"(a));
}
__device__ __forceinline__ void mma_bf16(float* d, const uint32_t* a, const uint32_t* b) {
    asm volatile("mma.sync.aligned.m16n8k16.row.col.f32.bf16.bf16.f32 "
        "{%0,%1,%2,%3}, {%4,%5,%6,%7}, {%8,%9}, {%0,%1,%2,%3};"
        : "+f"(d[0]), "+f"(d[1]), "+f"(d[2]), "+f"(d[3])
        : "r"(a[0]), "r"(a[1]), "r"(a[2]), "r"(a[3]), "r"(b[0]), "r"(b[1]));
}
__device__ __forceinline__ uint32_t pack_bf(__nv_bfloat16 lo, __nv_bfloat16 hi) {
    return (uint32_t)__bfloat16_as_ushort(lo) | ((uint32_t)__bfloat16_as_ushort(hi) << 16);
}
__device__ __forceinline__ void split2(float v, __nv_bfloat16& a, __nv_bfloat16& b) {
    a = __float2bfloat16(v);
    b = __float2bfloat16(v - __bfloat162float(a));
}

// ---------------- persistent LSTM (HMMA, in-warp combine) ----------------
// grid 148 (>=128 exit): jg = blockIdx>>3 (16 hid-tiles of 16), bg = blockIdx&7 (8 batch-tiles of 32)
// M=64 gate rows (m = jh*4 + gate), N=32, K=256. 512 threads = 16 warps (4 mt x 4 nt).
#define WSP_OFF  0                    // bf16 [2][m=64][k pad 264]
#define WSP_SPL  33792
#define HSP_OFF  67584                // bf16 [k=256][n pad 40]
#define WGS_OFF  88064                // per-warp f32 [16][10] (640B each)
#define LSTM_SMEM_BYTES 98304

__global__ void __launch_bounds__(512, 1)
lstm_kernel(const float* __restrict__ W_hh,
            const float* __restrict__ b_ih, const float* __restrict__ b_hh)
{
    extern __shared__ char smc[];
    if (blockIdx.x >= 128) return;
    const uint32_t sbase = smem_u32(smc);

    const int tid = threadIdx.x;
    const int bg  = blockIdx.x & 7;
    const int jg  = blockIdx.x >> 3;

    // one-time W staging: m = jh*4 + gate, 2 exact bf16 splits, [m=64][k pad 264]
    {
        int m = tid >> 3, kc = tid & 7;
        int j = (m & 3) * 256 + (jg << 4) + (m >> 2);      // gate*256 + jh_full
        const float* wrow = W_hh + (size_t)j * 256;
#pragma unroll
        for (int q = 0; q < 4; ++q) {
            int k0 = kc * 32 + q * 8;
            float4 u0 = *reinterpret_cast<const float4*>(wrow + k0);
            float4 u1 = *reinterpret_cast<const float4*>(wrow + k0 + 4);
            __nv_bfloat16 a[8], b[8];
            split2(u0.x, a[0], b[0]); split2(u0.y, a[1], b[1]);
            split2(u0.z, a[2], b[2]); split2(u0.w, a[3], b[3]);
            split2(u1.x, a[4], b[4]); split2(u1.y, a[5], b[5]);
            split2(u1.z, a[6], b[6]); split2(u1.w, a[7], b[7]);
            uint4 qa = make_uint4(pack_bf(a[0], a[1]), pack_bf(a[2], a[3]),
                                  pack_bf(a[4], a[5]), pack_bf(a[6], a[7]));
            uint4 qb = make_uint4(pack_bf(b[0], b[1]), pack_bf(b[2], b[3]),
                                  pack_bf(b[4], b[5]), pack_bf(b[6], b[7]));
            *reinterpret_cast<uint4*>(smc + WSP_OFF + m * 528 + k0 * 2) = qa;
            *reinterpret_cast<uint4*>(smc + WSP_OFF + WSP_SPL + m * 528 + k0 * 2) = qb;
        }
    }
    __syncthreads();

    // roles
    const int wid  = tid >> 5;
    const int lane = tid & 31;
    const int mt = wid >> 2, nt = wid & 3;
    const uint32_t aA0 = sbase + WSP_OFF +
        (uint32_t)(mt * 16 + (lane & 15)) * 528 + ((lane >> 4) * 16);
    const uint32_t aA1 = aA0 + WSP_SPL;
    const uint32_t aB0 = sbase + HSP_OFF + (uint32_t)(lane & 15) * 80 + nt * 16;
    float* wg = reinterpret_cast<float*>(smc + WGS_OFF + wid * 640);

    // combine cell: jh_full = jg*16 + mt*4 + jhl ; b = bg*32 + nt*8 + nl
    const int jhl = lane >> 3, nl = lane & 7;
    const int jh_full = (jg << 4) + mt * 4 + jhl;
    const int bcol = (bg << 5) + nt * 8 + nl;
    const size_t gxoff = (size_t)jh_full * 256 + bcol;
    const size_t hoff  = (size_t)jh_full * 256 + bcol;

    // per-cell constants in registers
    float bias_r[4];
#pragma unroll
    for (int g = 0; g < 4; ++g) {
        int j = g * 256 + jh_full;
        bias_r[g] = b_ih[j] + b_hh[j];
    }
    float creg = 0.f;

    // staging role
    const int sn4 = (tid & 7) << 2;
    const int skb = tid >> 3;

    for (int t = 0; t < NSTEP; ++t) {
        // early gx loads
        const float* gp = g_GX + (size_t)t * 262144 + gxoff;
        float gxi = ldcg1(gp);
        float gxf = ldcg1(gp + 65536);
        float gxg = ldcg1(gp + 131072);
        float gxo = ldcg1(gp + 196608);

        // stage h(t-1): bf16 copy g_Hb -> smem [k][n pad 40]
        if (t > 0) {
            const __nv_bfloat16* hb = g_Hb + (size_t)(t - 1) * 65536 + (bg << 5) + sn4;
#pragma unroll
            for (int i = 0; i < 4; ++i) {
                int k = skb + (i << 6);
                uint2 v = ldcg2u(hb + (size_t)k * 256);
                *reinterpret_cast<uint2*>(smc + HSP_OFF + k * 80 + sn4 * 2) = v;
            }
        }
        __syncthreads();

        // tensor GEMM + in-warp combine
        float gi = 0.f, gf = 0.f, gg = 0.f, go = 0.f;
        if (t > 0) {
            float d[4] = {0.f, 0.f, 0.f, 0.f};
#pragma unroll
            for (int kk = 0; kk < 16; ++kk) {
                uint32_t a0[4], a1[4], b0[2];
                ldsm4(a0, aA0 + kk * 32);
                ldsm4(a1, aA1 + kk * 32);
                ldsm2t(b0, aB0 + kk * 1280);
                mma_bf16(d, a0, b0);
                mma_bf16(d, a1, b0);
            }
            // dump D tile into per-warp patch [16][10]
            int r0 = lane >> 2, c2 = (lane & 3) << 1;
            *reinterpret_cast<float2*>(wg + r0 * 10 + c2) = make_float2(d[0], d[1]);
            *reinterpret_cast<float2*>(wg + (r0 + 8) * 10 + c2) = make_float2(d[2], d[3]);
            __syncwarp();
            // conflict-free gather of this cell's 4 gates (rows jhl*4+g, col nl)
            gi = wg[(jhl * 4 + 0) * 10 + nl];
            gf = wg[(jhl * 4 + 1) * 10 + nl];
            gg = wg[(jhl * 4 + 2) * 10 + nl];
            go = wg[(jhl * 4 + 3) * 10 + nl];
        }
        // combine (c in register)
        {
            float iv = sigf(gxi + bias_r[0] + gi);
            float fv = sigf(gxf + bias_r[1] + gf);
            float gv = tanhfast(gxg + bias_r[2] + gg);
            float ov = sigf(gxo + bias_r[3] + go);
            float cv = fv * creg + iv * gv;
            creg = cv;
            float hv = ov * tanhfast(cv);
            g_H [(size_t)t * 65536 + hoff] = hv;
            g_Hb[(size_t)t * 65536 + hoff] = __float2bfloat16(hv);
        }
        __syncthreads();

        // inter-block barrier (16 jg-blocks sharing this bg)
        if (tid == 0) {
            __threadfence();
            asm volatile("red.release.gpu.global.add.u32 [%0],%1;"
                         :: "l"(&g_bar[bg]), "r"(1u) : "memory");
            unsigned target = (unsigned)(t + 1) << 4;
            unsigned v;
            for (;;) {
                asm volatile("ld.acquire.gpu.global.u32 %0,[%1];"
                             : "=r"(v) : "l"(&g_bar[bg]));
                if (v >= target) break;
                __nanosleep(32);
            }
        }
        __syncthreads();
    }
}

// ---------------- MDN head ----------------
__device__ __forceinline__ void mdn_gemm(
    const float* __restrict__ At, int ldA, int mTiles, int K,
    const float* __restrict__ Bs, int ldb, float* __restrict__ Cs,
    const float* __restrict__ biasv, bool relu)
{
    for (int tile = threadIdx.x; tile < mTiles * 8; tile += blockDim.x) {
        int tm = tile % mTiles, tb = tile / mTiles;
        int m = tm << 2;
        const float* Ap = At + m;
        const float* Bp = Bs + (tb << 2);
        float acc[4][4];
#pragma unroll
        for (int i = 0; i < 4; ++i)
#pragma unroll
            for (int j = 0; j < 4; ++j) acc[i][j] = 0.f;
#pragma unroll 4
        for (int k = 0; k < K; ++k) {
            float4 a  = *reinterpret_cast<const float4*>(Ap + k * ldA);
            float4 b4 = *reinterpret_cast<const float4*>(Bp + k * ldb);
            float av[4] = {a.x, a.y, a.z, a.w};
            float bv[4] = {b4.x, b4.y, b4.z, b4.w};
#pragma unroll
            for (int i = 0; i < 4; ++i)
#pragma unroll
                for (int j = 0; j < 4; ++j) acc[i][j] = fmaf(av[i], bv[j], acc[i][j]);
        }
#pragma unroll
        for (int i = 0; i < 4; ++i) {
            float bv = biasv[m + i];
            float4 r = make_float4(acc[i][0] + bv, acc[i][1] + bv,
                                   acc[i][2] + bv, acc[i][3] + bv);
            if (relu) { r.x = fmaxf(r.x, 0.f); r.y = fmaxf(r.y, 0.f);
                        r.z = fmaxf(r.z, 0.f); r.w = fmaxf(r.w, 0.f); }
            *reinterpret_cast<float4*>(&Cs[(m + i) * 36 + (tb << 2)]) = r;
        }
    }
}

#define MDN_SMEM_BYTES ((256*32 + 112*36 + 176*36) * 4)

__global__ void __launch_bounds__(256, 2)
mdn_kernel(float* __restrict__ out)
{
    extern __shared__ float sm[];
    float* hT = sm;                 // [256][32], reused as h2 [112][36]
    float* h1 = hT + 256 * 32;      // [112][36]
    float* o3 = h1 + 112 * 36;      // [176][36]

    const int tid = threadIdx.x;
    const int t   = blockIdx.x >> 3;
    const int bg  = blockIdx.x & 7;

    const float* hp = g_H + (size_t)t * 65536 + (bg << 5);
    for (int i = tid; i < 2048; i += 256) {
        int k = i >> 3, nb = i & 7;
        float4 v = *reinterpret_cast<const float4*>(hp + (size_t)k * 256 + (nb << 2));
        *reinterpret_cast<float4*>(&hT[k * 32 + (nb << 2)]) = v;
    }
    __syncthreads();

    mdn_gemm(g_W1t, 112, 28, 256, hT, 32, h1, g_b1p, true);
    __syncthreads();
    mdn_gemm(g_W2t, 112, 28, 112, h1, 36, hT, g_b2p, true);   // h2 -> hT (reuse)
    __syncthreads();
    mdn_gemm(g_W3t, 176, 44, 112, hT, 36, o3, g_b3p, false);
    __syncthreads();

    if (tid < 32) {
        int n = tid;
        size_t r = (size_t)((bg << 5) + n) * NSTEP + t;
        float l[5];
        float mx = -1e30f;
#pragma unroll
        for (int k = 0; k < 5; ++k) { l[k] = o3[k * 36 + n]; mx = fmaxf(mx, l[k]); }
        float s = 0.f;
#pragma unroll
        for (int k = 0; k < 5; ++k) { l[k] = __expf(l[k] - mx); s += l[k]; }
        float inv = 1.f / s;
#pragma unroll
        for (int k = 0; k < 5; ++k) out[r * 5 + k] = l[k] * inv;
#pragma unroll
        for (int k = 0; k < 5; ++k)
            out[VARBASE + r * 5 + k] = __expf(o3[(5 + k) * 36 + n]);
    }
    for (int i = tid; i < 5120; i += 256) {
        int n = i / 160, j = i - n * 160;
        size_t r = (size_t)((bg << 5) + n) * NSTEP + t;
        out[MEANBASE + r * 160 + j] = o3[(10 + j) * 36 + n];
    }
}

extern "C" void kernel_launch(void* const* d_in, const int* in_sizes, int n_in,
                              void* d_out, int out_size)
{
    const float* x    = (const float*)d_in[0];
    const float* W_ih = (const float*)d_in[1];
    const float* W_hh = (const float*)d_in[2];
    const float* b_ih = (const float*)d_in[3];
    const float* b_hh = (const float*)d_in[4];
    const float* W1   = (const float*)d_in[5];
    const float* b1   = (const float*)d_in[6];
    const float* W2   = (const float*)d_in[7];
    const float* b2   = (const float*)d_in[8];
    const float* W3   = (const float*)d_in[9];
    const float* b3   = (const float*)d_in[10];
    float* out = (float*)d_out;

    cudaFuncSetAttribute(lstm_kernel, cudaFuncAttributeMaxDynamicSharedMemorySize, LSTM_SMEM_BYTES);
    cudaFuncSetAttribute(mdn_kernel,  cudaFuncAttributeMaxDynamicSharedMemorySize, MDN_SMEM_BYTES);

    prep_w<<<128, 256>>>(W1, b1, W2, b2, W3, b3);
    xproj_kernel<<<dim3(NSTEP, 16, 4), 256>>>(x, W_ih);
    lstm_kernel<<<148, 512, LSTM_SMEM_BYTES>>>(W_hh, b_ih, b_hh);
    mdn_kernel<<<NSTEP * 8, 256, MDN_SMEM_BYTES>>>(out);
}